// round 13
// baseline (speedup 1.0000x reference)
#include <cuda_runtime.h>
#include <cuda_bf16.h>
#include <cstdint>
#include <math.h>

#define D_MODEL 1024
#define NH 16
#define HD 64
#define BB 2
#define SS 2048
#define MROWS (BB*SS)   // 4096
#define NPAIR (MROWS*D_MODEL/2)   // 2M uint32 pairs
#define WPAIR (D_MODEL*D_MODEL/2) // 512K uint32 pairs

// Scratch (allocation-free __device__ globals) — EXACT same set as R8 (80 MB).
// Aliased lifetimes (sequential launches order all hazards):
//   g_vth/g_vtl : A-split scratch for Q/K/V GEMMs, then V^T (vtrans output)
//   g_attn      : [0..2*WPAIR) words = W-split scratch for Q/K/V GEMMs,
//                 then fp32 attention output [B,S,D]
//   g_qh/g_ql   : Q split output, then A-split scratch for O GEMM
//   g_kh/g_kl   : K split output, then W-split scratch for O GEMM
__device__ uint32_t g_qh[NPAIR], g_ql[NPAIR];     // [B,H,S,Dh/2]
__device__ uint32_t g_kh[NPAIR], g_kl[NPAIR];
__device__ uint32_t g_vh[NPAIR], g_vl[NPAIR];
__device__ uint32_t g_vth[NPAIR], g_vtl[NPAIR];   // [B,H,Dh,S/2]
__device__ float    g_attn[(size_t)MROWS*D_MODEL];// [B,S,D]

// ============================================================================
// helpers
// ============================================================================
__device__ __forceinline__ uint32_t pack_bf2(__nv_bfloat16 a, __nv_bfloat16 b) {
    __nv_bfloat162 v; v.x = a; v.y = b;
    return *(uint32_t*)&v;
}
__device__ __forceinline__ void bsplit2(float x, float y, uint32_t& hi, uint32_t& lo) {
    __nv_bfloat16 hx = __float2bfloat16_rn(x);
    __nv_bfloat16 hy = __float2bfloat16_rn(y);
    __nv_bfloat16 lx = __float2bfloat16_rn(x - __bfloat162float(hx));
    __nv_bfloat16 ly = __float2bfloat16_rn(y - __bfloat162float(hy));
    hi = pack_bf2(hx, hy);
    lo = pack_bf2(lx, ly);
}

#define MMA_BF16(dd, a0,a1,a2,a3, b0,b1) \
    asm volatile( \
        "mma.sync.aligned.m16n8k16.row.col.f32.bf16.bf16.f32 " \
        "{%0,%1,%2,%3}, {%4,%5,%6,%7}, {%8,%9}, {%0,%1,%2,%3};" \
        : "+f"((dd)[0]), "+f"((dd)[1]), "+f"((dd)[2]), "+f"((dd)[3]) \
        : "r"(a0), "r"(a1), "r"(a2), "r"(a3), "r"(b0), "r"(b1))

// ============================================================================
// Split kernel: fp32 -> bf16 hi/lo pair arrays into aliased scratch.
// sel 0: src -> g_vth/g_vtl              (A for Q/K/V gemms)
// sel 1: src -> g_attn[0..WPAIR)/[WPAIR..2*WPAIR) as uint32  (W for Q/K/V)
// sel 2: src -> g_kh/g_kl                (W for O gemm)
// sel 3: g_attn (fp32) -> g_qh/g_ql      (A for O gemm; src param ignored)
// ============================================================================
__global__ __launch_bounds__(256)
void split_kernel(const float* __restrict__ src, int sel)
{
    int idx = blockIdx.x * 256 + threadIdx.x;     // float4 index
    const float* s = (sel == 3) ? g_attn : src;
    uint32_t* dh;
    uint32_t* dl;
    if (sel == 0)      { dh = g_vth; dl = g_vtl; }
    else if (sel == 1) { dh = (uint32_t*)g_attn; dl = (uint32_t*)g_attn + WPAIR; }
    else if (sel == 2) { dh = g_kh;  dl = g_kl;  }
    else               { dh = g_qh;  dl = g_ql;  }

    float4 v = *(const float4*)(s + (size_t)idx * 4);
    uint32_t h0, l0, h1, l1;
    bsplit2(v.x, v.y, h0, l0);
    bsplit2(v.z, v.w, h1, l1);
    *(uint2*)&dh[(size_t)idx * 2] = make_uint2(h0, h1);
    *(uint2*)&dl[(size_t)idx * 2] = make_uint2(l0, l1);
}

// ============================================================================
// Split-bf16 GEMM (pre-split operands): C = A @ W^T + bias.
// Tile 128x128, K-chunk 32 (16 pairs). Static smem, single stage.
// mode 0/1/2: A=g_vth/g_vtl, W=g_attn-scratch -> q/k/v split pair outputs
// mode 3:     A=g_qh/g_ql,  W=g_kh/g_kl      -> fp32 Cout
// ============================================================================
#define GP 20   // pair stride (16 + 4 pad): 80B rows, 16B-aligned

__global__ __launch_bounds__(256)
void tc_gemm(const float* __restrict__ bias, float* __restrict__ Cout, int mode)
{
    __shared__ uint32_t Ah[128 * GP], Al[128 * GP], Bh[128 * GP], Bl[128 * GP]; // 40,960 B

    const int tid  = threadIdx.x;
    const int wid  = tid >> 5;
    const int lane = tid & 31;
    const int wm   = (wid & 3) << 5;
    const int wn   = (wid >> 2) << 6;
    const int gr   = lane >> 2;
    const int gc   = lane & 3;

    const int bm = blockIdx.y * 128;
    const int bn = blockIdx.x * 128;

    const uint32_t* Ahp;
    const uint32_t* Alp;
    const uint32_t* Whp;
    const uint32_t* Wlp;
    if (mode <= 2) {
        Ahp = g_vth; Alp = g_vtl;
        Whp = (const uint32_t*)g_attn; Wlp = (const uint32_t*)g_attn + WPAIR;
    } else {
        Ahp = g_qh; Alp = g_ql;
        Whp = g_kh; Wlp = g_kl;
    }

    float acc[2][8][4];
    #pragma unroll
    for (int mt = 0; mt < 2; mt++)
        #pragma unroll
        for (int nt = 0; nt < 8; nt++)
            #pragma unroll
            for (int r = 0; r < 4; r++) acc[mt][nt][r] = 0.f;

    for (int c = 0; c < 32; c++) {
        __syncthreads();
        // load chunk: 512 uint4 per array, 2 per thread
        #pragma unroll
        for (int i = 0; i < 2; i++) {
            int lin = i * 256 + tid;          // 0..511
            int row = lin >> 2;               // 0..127
            int c4  = (lin & 3) << 2;         // word offset 0,4,8,12
            int so  = row * GP + c4;
            size_t ai = (size_t)(bm + row) * 512 + c * 16 + c4;
            size_t wi = (size_t)(bn + row) * 512 + c * 16 + c4;
            *(uint4*)&Ah[so] = *(const uint4*)(Ahp + ai);
            *(uint4*)&Al[so] = *(const uint4*)(Alp + ai);
            *(uint4*)&Bh[so] = *(const uint4*)(Whp + wi);
            *(uint4*)&Bl[so] = *(const uint4*)(Wlp + wi);
        }
        __syncthreads();

        #pragma unroll
        for (int ks = 0; ks < 2; ks++) {
            const int kp = ks * 8 + gc;
            uint32_t ah[2][4], al[2][4];
            #pragma unroll
            for (int mt = 0; mt < 2; mt++) {
                int r0 = (wm + mt * 16 + gr) * GP + kp;
                int r8 = r0 + 8 * GP;
                ah[mt][0] = Ah[r0]; ah[mt][1] = Ah[r8];
                ah[mt][2] = Ah[r0 + 4]; ah[mt][3] = Ah[r8 + 4];
                al[mt][0] = Al[r0]; al[mt][1] = Al[r8];
                al[mt][2] = Al[r0 + 4]; al[mt][3] = Al[r8 + 4];
            }
            #pragma unroll
            for (int nt = 0; nt < 8; nt++) {
                int n0 = (wn + nt * 8 + gr) * GP + kp;
                uint32_t bh0 = Bh[n0], bh1 = Bh[n0 + 4];
                uint32_t bl0 = Bl[n0], bl1 = Bl[n0 + 4];
                #pragma unroll
                for (int mt = 0; mt < 2; mt++) {
                    float* d = acc[mt][nt];
                    MMA_BF16(d, ah[mt][0], ah[mt][1], ah[mt][2], ah[mt][3], bl0, bl1);
                    MMA_BF16(d, al[mt][0], al[mt][1], al[mt][2], al[mt][3], bh0, bh1);
                    MMA_BF16(d, ah[mt][0], ah[mt][1], ah[mt][2], ah[mt][3], bh0, bh1);
                }
            }
        }
    }

    // epilogue
    uint32_t* Hp = (mode == 0) ? g_qh : (mode == 1) ? g_kh : g_vh;
    uint32_t* Lp = (mode == 0) ? g_ql : (mode == 1) ? g_kl : g_vl;
    #pragma unroll
    for (int mt = 0; mt < 2; mt++) {
        #pragma unroll
        for (int nt = 0; nt < 8; nt++) {
            int m0 = bm + wm + mt * 16 + gr;
            int n0 = bn + wn + nt * 8 + gc * 2;
            float b0 = bias[n0], b1 = bias[n0 + 1];
            #pragma unroll
            for (int half = 0; half < 2; half++) {
                int m = m0 + half * 8;
                float v0 = acc[mt][nt][half * 2 + 0] + b0;
                float v1 = acc[mt][nt][half * 2 + 1] + b1;
                if (mode <= 2) {
                    int b = m >> 11;
                    int s = m & (SS - 1);
                    int h = n0 >> 6;
                    int d = n0 & (HD - 1);
                    size_t pidx = (((size_t)(b * NH + h) * SS + s) * HD + d) >> 1;
                    uint32_t hi, lo;
                    bsplit2(v0, v1, hi, lo);
                    Hp[pidx] = hi;
                    Lp[pidx] = lo;
                } else {
                    *(float2*)(Cout + (size_t)m * D_MODEL + n0) = make_float2(v0, v1);
                }
            }
        }
    }
}

// ============================================================================
// V transpose: g_vh/g_vl [b,h,s,d-pairs] -> g_vth/g_vtl [b,h,d,s-pairs]
// ============================================================================
#define TP 36

__global__ __launch_bounds__(128)
void vtrans_kernel()
{
    __shared__ uint32_t th[64 * TP], tl[64 * TP];
    const int t  = threadIdx.x;
    const int s0 = blockIdx.x * 64;
    const int h  = blockIdx.y;
    const int b  = blockIdx.z;
    const size_t bh = (size_t)(b * NH + h);

    const uint4* src_h = (const uint4*)g_vh;
    const uint4* src_l = (const uint4*)g_vl;
    #pragma unroll
    for (int i = 0; i < 4; i++) {
        int lin = i * 128 + t;
        int row = lin >> 3;
        int c4  = (lin & 7) << 2;
        size_t si = (bh * SS + s0 + row) * 8 + (c4 >> 2);
        *(uint4*)&th[row * TP + c4] = src_h[si];
        *(uint4*)&tl[row * TP + c4] = src_l[si];
    }
    __syncthreads();

    const __nv_bfloat16* thb = (const __nv_bfloat16*)th;
    const __nv_bfloat16* tlb = (const __nv_bfloat16*)tl;
    const int sp = t & 31;
    const int dr = t >> 5;
    #pragma unroll
    for (int i = 0; i < 16; i++) {
        int d = i * 4 + dr;
        __nv_bfloat16 h0 = thb[(2 * sp) * (2 * TP) + d];
        __nv_bfloat16 h1 = thb[(2 * sp + 1) * (2 * TP) + d];
        __nv_bfloat16 l0 = tlb[(2 * sp) * (2 * TP) + d];
        __nv_bfloat16 l1 = tlb[(2 * sp + 1) * (2 * TP) + d];
        size_t di = (bh * HD + d) * (SS / 2) + (s0 >> 1) + sp;
        g_vth[di] = pack_bf2(h0, h1);
        g_vtl[di] = pack_bf2(l0, l1);
    }
}

// ============================================================================
// Tensor-core flash attention (exact R8 config: 128 threads, 64 q rows).
// ============================================================================
#define PST 36

__global__ __launch_bounds__(128)
void attn_kernel(const int* __restrict__ mask)
{
    __shared__ uint32_t Kh[64 * PST], Kl[64 * PST], Vh[64 * PST], Vl[64 * PST];

    const int t    = threadIdx.x;
    const int wid  = t >> 5;
    const int lane = t & 31;
    const int gr   = lane >> 2;
    const int gc   = lane & 3;
    const int wm   = wid * 16;
    const int q0   = blockIdx.x * 64;
    const int h    = blockIdx.y;
    const int b    = blockIdx.z;
    const float scale = 0.125f;

    const size_t bh = (size_t)(b * NH + h);
    const uint32_t* qhp = g_qh + bh * SS * (HD / 2);
    const uint32_t* qlp = g_ql + bh * SS * (HD / 2);
    const uint32_t* khp = g_kh + bh * SS * (HD / 2);
    const uint32_t* klp = g_kl + bh * SS * (HD / 2);
    const uint32_t* vhp = g_vth + bh * HD * (SS / 2);
    const uint32_t* vlp = g_vtl + bh * HD * (SS / 2);

    uint32_t qh[4][4], ql[4][4];
    {
        int r0 = (q0 + wm + gr) * 32;
        int r1 = r0 + 8 * 32;
        #pragma unroll
        for (int ks = 0; ks < 4; ks++) {
            int p = ks * 8 + gc;
            qh[ks][0] = qhp[r0 + p];     qh[ks][1] = qhp[r1 + p];
            qh[ks][2] = qhp[r0 + p + 4]; qh[ks][3] = qhp[r1 + p + 4];
            ql[ks][0] = qlp[r0 + p];     ql[ks][1] = qlp[r1 + p];
            ql[ks][2] = qlp[r0 + p + 4]; ql[ks][3] = qlp[r1 + p + 4];
        }
    }

    float oacc[8][4];
    #pragma unroll
    for (int dt = 0; dt < 8; dt++)
        #pragma unroll
        for (int r = 0; r < 4; r++) oacc[dt][r] = 0.f;
    float m0 = -1e30f, m1 = -1e30f, l0 = 0.f, l1 = 0.f;

    for (int k0 = 0; k0 < SS; k0 += 64) {
        __syncthreads();

        #pragma unroll
        for (int i = 0; i < 4; i++) {
            int lin = i * 128 + t;
            int row = lin >> 3;
            int c4  = (lin & 7) << 2;
            int so  = row * PST + c4;
            *(uint4*)&Kh[so] = *(const uint4*)(khp + (size_t)(k0 + row) * 32 + c4);
            *(uint4*)&Kl[so] = *(const uint4*)(klp + (size_t)(k0 + row) * 32 + c4);
            *(uint4*)&Vh[so] = *(const uint4*)(vhp + (size_t)row * (SS / 2) + (k0 >> 1) + c4);
            *(uint4*)&Vl[so] = *(const uint4*)(vlp + (size_t)row * (SS / 2) + (k0 >> 1) + c4);
        }
        __syncthreads();

        float c[8][4];
        #pragma unroll
        for (int nt = 0; nt < 8; nt++)
            #pragma unroll
            for (int r = 0; r < 4; r++) c[nt][r] = 0.f;

        #pragma unroll
        for (int ks = 0; ks < 4; ks++) {
            #pragma unroll
            for (int nt = 0; nt < 8; nt++) {
                int bi = (nt * 8 + gr) * PST + ks * 8 + gc;
                uint32_t bh0 = Kh[bi], bh1 = Kh[bi + 4];
                uint32_t bl0 = Kl[bi], bl1 = Kl[bi + 4];
                MMA_BF16(c[nt], qh[ks][0], qh[ks][1], qh[ks][2], qh[ks][3], bl0, bl1);
                MMA_BF16(c[nt], ql[ks][0], ql[ks][1], ql[ks][2], ql[ks][3], bh0, bh1);
                MMA_BF16(c[nt], qh[ks][0], qh[ks][1], qh[ks][2], qh[ks][3], bh0, bh1);
            }
        }

        const int* mrow0 = mask + (size_t)(q0 + wm + gr) * SS + k0;
        const int* mrow1 = mrow0 + 8 * SS;
        #pragma unroll
        for (int nt = 0; nt < 8; nt++) {
            int col = nt * 8 + 2 * gc;
            int2 mv0 = *(const int2*)(mrow0 + col);
            int2 mv1 = *(const int2*)(mrow1 + col);
            c[nt][0] = mv0.x ? c[nt][0] * scale : -10000.f;
            c[nt][1] = mv0.y ? c[nt][1] * scale : -10000.f;
            c[nt][2] = mv1.x ? c[nt][2] * scale : -10000.f;
            c[nt][3] = mv1.y ? c[nt][3] * scale : -10000.f;
        }

        float mx0 = -1e30f, mx1 = -1e30f;
        #pragma unroll
        for (int nt = 0; nt < 8; nt++) {
            mx0 = fmaxf(mx0, fmaxf(c[nt][0], c[nt][1]));
            mx1 = fmaxf(mx1, fmaxf(c[nt][2], c[nt][3]));
        }
        mx0 = fmaxf(mx0, __shfl_xor_sync(0xFFFFFFFF, mx0, 1));
        mx0 = fmaxf(mx0, __shfl_xor_sync(0xFFFFFFFF, mx0, 2));
        mx1 = fmaxf(mx1, __shfl_xor_sync(0xFFFFFFFF, mx1, 1));
        mx1 = fmaxf(mx1, __shfl_xor_sync(0xFFFFFFFF, mx1, 2));

        float mn0 = fmaxf(m0, mx0), mn1 = fmaxf(m1, mx1);
        float al0 = __expf(m0 - mn0), al1 = __expf(m1 - mn1);
        l0 *= al0; l1 *= al1;
        #pragma unroll
        for (int dt = 0; dt < 8; dt++) {
            oacc[dt][0] *= al0; oacc[dt][1] *= al0;
            oacc[dt][2] *= al1; oacc[dt][3] *= al1;
        }

        float s0 = 0.f, s1 = 0.f;
        #pragma unroll
        for (int nt = 0; nt < 8; nt++) {
            c[nt][0] = __expf(c[nt][0] - mn0);
            c[nt][1] = __expf(c[nt][1] - mn0);
            c[nt][2] = __expf(c[nt][2] - mn1);
            c[nt][3] = __expf(c[nt][3] - mn1);
            s0 += c[nt][0] + c[nt][1];
            s1 += c[nt][2] + c[nt][3];
        }
        s0 += __shfl_xor_sync(0xFFFFFFFF, s0, 1);
        s0 += __shfl_xor_sync(0xFFFFFFFF, s0, 2);
        s1 += __shfl_xor_sync(0xFFFFFFFF, s1, 1);
        s1 += __shfl_xor_sync(0xFFFFFFFF, s1, 2);
        l0 += s0; l1 += s1;
        m0 = mn0; m1 = mn1;

        #pragma unroll
        for (int ks = 0; ks < 4; ks++) {
            uint32_t pah[4], pal[4];
            bsplit2(c[2*ks][0],   c[2*ks][1],   pah[0], pal[0]);
            bsplit2(c[2*ks][2],   c[2*ks][3],   pah[1], pal[1]);
            bsplit2(c[2*ks+1][0], c[2*ks+1][1], pah[2], pal[2]);
            bsplit2(c[2*ks+1][2], c[2*ks+1][3], pah[3], pal[3]);
            #pragma unroll
            for (int dt = 0; dt < 8; dt++) {
                int bi = (dt * 8 + gr) * PST + ks * 8 + gc;
                uint32_t bh0 = Vh[bi], bh1 = Vh[bi + 4];
                uint32_t bl0 = Vl[bi], bl1 = Vl[bi + 4];
                MMA_BF16(oacc[dt], pah[0], pah[1], pah[2], pah[3], bl0, bl1);
                MMA_BF16(oacc[dt], pal[0], pal[1], pal[2], pal[3], bh0, bh1);
                MMA_BF16(oacc[dt], pah[0], pah[1], pah[2], pah[3], bh0, bh1);
            }
        }
    }

    float inv0 = 1.f / l0, inv1 = 1.f / l1;
    float* orow0 = g_attn + ((size_t)b * SS + q0 + wm + gr) * D_MODEL + h * HD;
    float* orow1 = orow0 + 8 * D_MODEL;
    #pragma unroll
    for (int dt = 0; dt < 8; dt++) {
        int col = dt * 8 + 2 * gc;
        *(float2*)(orow0 + col) = make_float2(oacc[dt][0] * inv0, oacc[dt][1] * inv0);
        *(float2*)(orow1 + col) = make_float2(oacc[dt][2] * inv1, oacc[dt][3] * inv1);
    }
}

// ============================================================================
extern "C" void kernel_launch(void* const* d_in, const int* in_sizes, int n_in,
                              void* d_out, int out_size)
{
    const float* q    = (const float*)d_in[0];
    const float* k    = (const float*)d_in[1];
    const float* v    = (const float*)d_in[2];
    const int*   mask = (const int*)  d_in[3];
    const float* wq   = (const float*)d_in[4];
    const float* bq   = (const float*)d_in[5];
    const float* wk   = (const float*)d_in[6];
    const float* bk   = (const float*)d_in[7];
    const float* wv   = (const float*)d_in[8];
    const float* bv   = (const float*)d_in[9];
    const float* wo   = (const float*)d_in[10];
    const float* bo   = (const float*)d_in[11];
    float* out = (float*)d_out;

    const int GA = MROWS * D_MODEL / 4 / 256;     // 4096 blocks (A-sized split)
    const int GW = D_MODEL * D_MODEL / 4 / 256;   // 1024 blocks (W-sized split)
    dim3 gg(D_MODEL / 128, MROWS / 128);          // (8, 32)

    split_kernel<<<GA, 256>>>(q, 0);
    split_kernel<<<GW, 256>>>(wq, 1);
    tc_gemm<<<gg, 256>>>(bq, nullptr, 0);

    split_kernel<<<GA, 256>>>(k, 0);
    split_kernel<<<GW, 256>>>(wk, 1);
    tc_gemm<<<gg, 256>>>(bk, nullptr, 1);

    split_kernel<<<GA, 256>>>(v, 0);
    split_kernel<<<GW, 256>>>(wv, 1);
    tc_gemm<<<gg, 256>>>(bv, nullptr, 2);

    vtrans_kernel<<<dim3(SS / 64, NH, BB), 128>>>();
    attn_kernel<<<dim3(SS / 64, NH, BB), 128>>>(mask);

    split_kernel<<<GA, 256>>>(q, 3);      // src ignored: g_attn -> g_qh/g_ql
    split_kernel<<<GW, 256>>>(wo, 2);     // wo -> g_kh/g_kl
    tc_gemm<<<gg, 256>>>(bo, out, 3);
}

// round 14
// speedup vs baseline: 1.0947x; 1.0947x over previous
#include <cuda_runtime.h>
#include <cuda_bf16.h>
#include <cstdint>
#include <math.h>

#define D_MODEL 1024
#define NH 16
#define HD 64
#define BB 2
#define SS 2048
#define MROWS (BB*SS)   // 4096
#define NPAIR (MROWS*D_MODEL/2)   // 2M uint32 pairs per tensor

// Scratch (allocation-free __device__ globals)
// Split-bf16 pair arrays: hi/lo packed as bf16x2 (pairs along last dim)
__device__ uint32_t g_qh[NPAIR], g_ql[NPAIR];     // [B,H,S,Dh/2]
__device__ uint32_t g_kh[NPAIR], g_kl[NPAIR];     // [B,H,S,Dh/2]
__device__ uint32_t g_vh[NPAIR], g_vl[NPAIR];     // [B,H,S,Dh/2]
__device__ uint32_t g_vth[NPAIR], g_vtl[NPAIR];   // [B,H,Dh,S/2]  (V transposed)
__device__ float    g_attn[(size_t)MROWS*D_MODEL];// [B,S,D]

// ============================================================================
// helpers
// ============================================================================
__device__ __forceinline__ uint32_t pack_bf2(__nv_bfloat16 a, __nv_bfloat16 b) {
    __nv_bfloat162 v; v.x = a; v.y = b;
    return *(uint32_t*)&v;
}
// split (x,y) into packed bf16x2 hi + residual lo
__device__ __forceinline__ void bsplit2(float x, float y, uint32_t& hi, uint32_t& lo) {
    __nv_bfloat16 hx = __float2bfloat16_rn(x);
    __nv_bfloat16 hy = __float2bfloat16_rn(y);
    __nv_bfloat16 lx = __float2bfloat16_rn(x - __bfloat162float(hx));
    __nv_bfloat16 ly = __float2bfloat16_rn(y - __bfloat162float(hy));
    hi = pack_bf2(hx, hy);
    lo = pack_bf2(lx, ly);
}

// mma.sync m16n8k16 bf16: D += A*B (A row-major 16x16, B col-major 16x8)
#define MMA_BF16(dd, a0,a1,a2,a3, b0,b1) \
    asm volatile( \
        "mma.sync.aligned.m16n8k16.row.col.f32.bf16.bf16.f32 " \
        "{%0,%1,%2,%3}, {%4,%5,%6,%7}, {%8,%9}, {%0,%1,%2,%3};" \
        : "+f"((dd)[0]), "+f"((dd)[1]), "+f"((dd)[2]), "+f"((dd)[3]) \
        : "r"(a0), "r"(a1), "r"(a2), "r"(a3), "r"(b0), "r"(b1))

// ============================================================================
// Split-bf16 tensor-core GEMM: C[M,N] = A[M,K] @ W[N,K]^T + bias
// M=4096, N=K=1024. Block tile 128x128, K-chunk 32 (2 k16 steps).
// 3 products: ah*bh + ah*bl + al*bh  (~16-bit effective mantissa).
// __launch_bounds__(256, 2): cap 128 regs/thread -> 2 CTAs/SM so the
// per-chunk LDG->convert->STS->MMA serial chain overlaps across CTAs.
// mode 0/1/2: write split-bf16 pairs (q/k/v) in [B,H,S,Dh]; mode 3: f32 out.
// ============================================================================
#define GP 18   // pair stride per row (16 + 2 pad)

__global__ __launch_bounds__(256, 2)
void tc_gemm(const float* __restrict__ A, const float* __restrict__ W,
             const float* __restrict__ bias, float* __restrict__ Cout, int mode)
{
    __shared__ uint32_t sh[4 * 128 * GP];   // 36,864 B
    uint32_t* Ah = sh;
    uint32_t* Al = sh + 1 * 128 * GP;
    uint32_t* Bh = sh + 2 * 128 * GP;
    uint32_t* Bl = sh + 3 * 128 * GP;

    const int tid  = threadIdx.x;
    const int wid  = tid >> 5;
    const int lane = tid & 31;
    const int wm   = (wid & 3) << 5;
    const int wn   = (wid >> 2) << 6;
    const int gr   = lane >> 2;
    const int gc   = lane & 3;

    const float* Ap = (mode == 3) ? g_attn : A;
    const int bm = blockIdx.y * 128;
    const int bn = blockIdx.x * 128;

    float acc[2][8][4];
    #pragma unroll
    for (int mt = 0; mt < 2; mt++)
        #pragma unroll
        for (int nt = 0; nt < 8; nt++)
            #pragma unroll
            for (int r = 0; r < 4; r++) acc[mt][nt][r] = 0.f;

    for (int k0 = 0; k0 < D_MODEL; k0 += 32) {
        __syncthreads();
        #pragma unroll
        for (int i = 0; i < 4; i++) {
            int lin = i * 256 + tid;          // 0..1023
            int row = lin >> 3;               // 0..127
            int c4  = (lin & 7) << 2;         // 0..28 (f32 col)
            int so  = row * GP + (c4 >> 1);   // pair index

            float4 a = *(const float4*)(Ap + (size_t)(bm + row) * D_MODEL + k0 + c4);
            uint32_t h0, l0, h1, l1;
            bsplit2(a.x, a.y, h0, l0);
            bsplit2(a.z, a.w, h1, l1);
            *(uint2*)&Ah[so] = make_uint2(h0, h1);
            *(uint2*)&Al[so] = make_uint2(l0, l1);

            float4 b = *(const float4*)(W + (size_t)(bn + row) * D_MODEL + k0 + c4);
            bsplit2(b.x, b.y, h0, l0);
            bsplit2(b.z, b.w, h1, l1);
            *(uint2*)&Bh[so] = make_uint2(h0, h1);
            *(uint2*)&Bl[so] = make_uint2(l0, l1);
        }
        __syncthreads();

        #pragma unroll
        for (int ks = 0; ks < 2; ks++) {
            const int kp = ks * 8 + gc;
            uint32_t ah[2][4], al[2][4];
            #pragma unroll
            for (int mt = 0; mt < 2; mt++) {
                int r0 = (wm + mt * 16 + gr) * GP + kp;
                int r8 = r0 + 8 * GP;
                ah[mt][0] = Ah[r0]; ah[mt][1] = Ah[r8];
                ah[mt][2] = Ah[r0 + 4]; ah[mt][3] = Ah[r8 + 4];
                al[mt][0] = Al[r0]; al[mt][1] = Al[r8];
                al[mt][2] = Al[r0 + 4]; al[mt][3] = Al[r8 + 4];
            }
            #pragma unroll
            for (int nt = 0; nt < 8; nt++) {
                int n0 = (wn + nt * 8 + gr) * GP + kp;
                uint32_t bh0 = Bh[n0], bh1 = Bh[n0 + 4];
                uint32_t bl0 = Bl[n0], bl1 = Bl[n0 + 4];
                #pragma unroll
                for (int mt = 0; mt < 2; mt++) {
                    float* d = acc[mt][nt];
                    MMA_BF16(d, ah[mt][0], ah[mt][1], ah[mt][2], ah[mt][3], bl0, bl1);
                    MMA_BF16(d, al[mt][0], al[mt][1], al[mt][2], al[mt][3], bh0, bh1);
                    MMA_BF16(d, ah[mt][0], ah[mt][1], ah[mt][2], ah[mt][3], bh0, bh1);
                }
            }
        }
    }

    // epilogue
    uint32_t* Hp = (mode == 0) ? g_qh : (mode == 1) ? g_kh : g_vh;
    uint32_t* Lp = (mode == 0) ? g_ql : (mode == 1) ? g_kl : g_vl;
    #pragma unroll
    for (int mt = 0; mt < 2; mt++) {
        #pragma unroll
        for (int nt = 0; nt < 8; nt++) {
            int m0 = bm + wm + mt * 16 + gr;
            int n0 = bn + wn + nt * 8 + gc * 2;   // even
            float b0 = bias[n0], b1 = bias[n0 + 1];
            #pragma unroll
            for (int half = 0; half < 2; half++) {
                int m = m0 + half * 8;
                float v0 = acc[mt][nt][half * 2 + 0] + b0;
                float v1 = acc[mt][nt][half * 2 + 1] + b1;
                if (mode <= 2) {
                    int b = m >> 11;
                    int s = m & (SS - 1);
                    int h = n0 >> 6;
                    int d = n0 & (HD - 1);
                    size_t pidx = (((size_t)(b * NH + h) * SS + s) * HD + d) >> 1;
                    uint32_t hi, lo;
                    bsplit2(v0, v1, hi, lo);
                    Hp[pidx] = hi;
                    Lp[pidx] = lo;
                } else {
                    *(float2*)(Cout + (size_t)m * D_MODEL + n0) = make_float2(v0, v1);
                }
            }
        }
    }
}

// ============================================================================
// V transpose: g_vh/g_vl [b,h,s,d-pairs] -> g_vth/g_vtl [b,h,d,s-pairs]
// ============================================================================
#define TP 36   // pair stride (32 + 4 pad), 144B = 9*16 aligned

__global__ __launch_bounds__(128)
void vtrans_kernel()
{
    __shared__ uint32_t th[64 * TP], tl[64 * TP];   // 2 x 9216 B
    const int t  = threadIdx.x;
    const int s0 = blockIdx.x * 64;
    const int h  = blockIdx.y;
    const int b  = blockIdx.z;
    const size_t bh = (size_t)(b * NH + h);

    const uint4* src_h = (const uint4*)g_vh;
    const uint4* src_l = (const uint4*)g_vl;
    #pragma unroll
    for (int i = 0; i < 4; i++) {
        int lin = i * 128 + t;            // 0..511
        int row = lin >> 3;               // 0..63
        int c4  = (lin & 7) << 2;         // pair idx 0..28
        size_t si = (bh * SS + s0 + row) * 8 + (c4 >> 2);
        *(uint4*)&th[row * TP + c4] = src_h[si];
        *(uint4*)&tl[row * TP + c4] = src_l[si];
    }
    __syncthreads();

    const __nv_bfloat16* thb = (const __nv_bfloat16*)th;
    const __nv_bfloat16* tlb = (const __nv_bfloat16*)tl;
    const int sp = t & 31;
    const int dr = t >> 5;                // 0..3
    #pragma unroll
    for (int i = 0; i < 16; i++) {
        int d = i * 4 + dr;               // 0..63
        __nv_bfloat16 h0 = thb[(2 * sp) * (2 * TP) + d];
        __nv_bfloat16 h1 = thb[(2 * sp + 1) * (2 * TP) + d];
        __nv_bfloat16 l0 = tlb[(2 * sp) * (2 * TP) + d];
        __nv_bfloat16 l1 = tlb[(2 * sp + 1) * (2 * TP) + d];
        size_t di = (bh * HD + d) * (SS / 2) + (s0 >> 1) + sp;
        g_vth[di] = pack_bf2(h0, h1);
        g_vtl[di] = pack_bf2(l0, l1);
    }
}

// ============================================================================
// Tensor-core flash attention. Block = 128 threads = 4 warps, 64 q rows
// (16/warp), KT=64. All operands pre-split bf16 in gmem; P stays in registers
// (QK D-fragment == PV A-fragment layout).
// ============================================================================
#define PST 36

__global__ __launch_bounds__(128)
void attn_kernel(const int* __restrict__ mask)
{
    __shared__ uint32_t Kh[64 * PST], Kl[64 * PST], Vh[64 * PST], Vl[64 * PST]; // 36,864 B

    const int t    = threadIdx.x;
    const int wid  = t >> 5;
    const int lane = t & 31;
    const int gr   = lane >> 2;
    const int gc   = lane & 3;
    const int wm   = wid * 16;
    const int q0   = blockIdx.x * 64;
    const int h    = blockIdx.y;
    const int b    = blockIdx.z;
    const float scale = 0.125f;

    const size_t bh = (size_t)(b * NH + h);
    const uint32_t* qhp = g_qh + bh * SS * (HD / 2);
    const uint32_t* qlp = g_ql + bh * SS * (HD / 2);
    const uint32_t* khp = g_kh + bh * SS * (HD / 2);
    const uint32_t* klp = g_kl + bh * SS * (HD / 2);
    const uint32_t* vhp = g_vth + bh * HD * (SS / 2);
    const uint32_t* vlp = g_vtl + bh * HD * (SS / 2);

    // Q fragments direct from split pairs
    uint32_t qh[4][4], ql[4][4];
    {
        int r0 = (q0 + wm + gr) * 32;
        int r1 = r0 + 8 * 32;
        #pragma unroll
        for (int ks = 0; ks < 4; ks++) {
            int p = ks * 8 + gc;
            qh[ks][0] = qhp[r0 + p];     qh[ks][1] = qhp[r1 + p];
            qh[ks][2] = qhp[r0 + p + 4]; qh[ks][3] = qhp[r1 + p + 4];
            ql[ks][0] = qlp[r0 + p];     ql[ks][1] = qlp[r1 + p];
            ql[ks][2] = qlp[r0 + p + 4]; ql[ks][3] = qlp[r1 + p + 4];
        }
    }

    float oacc[8][4];
    #pragma unroll
    for (int dt = 0; dt < 8; dt++)
        #pragma unroll
        for (int r = 0; r < 4; r++) oacc[dt][r] = 0.f;
    float m0 = -1e30f, m1 = -1e30f, l0 = 0.f, l1 = 0.f;

    for (int k0 = 0; k0 < SS; k0 += 64) {
        __syncthreads();   // prior PV done before overwriting tiles

        // bulk copy K and V^T tiles (bf16 pairs, no conversion)
        #pragma unroll
        for (int i = 0; i < 4; i++) {
            int lin = i * 128 + t;          // 0..511
            int row = lin >> 3;             // 0..63
            int c4  = (lin & 7) << 2;       // pair 0..28
            int so  = row * PST + c4;
            *(uint4*)&Kh[so] = *(const uint4*)(khp + (size_t)(k0 + row) * 32 + c4);
            *(uint4*)&Kl[so] = *(const uint4*)(klp + (size_t)(k0 + row) * 32 + c4);
            *(uint4*)&Vh[so] = *(const uint4*)(vhp + (size_t)row * (SS / 2) + (k0 >> 1) + c4);
            *(uint4*)&Vl[so] = *(const uint4*)(vlp + (size_t)row * (SS / 2) + (k0 >> 1) + c4);
        }
        __syncthreads();

        // ---- QK^T ----
        float c[8][4];
        #pragma unroll
        for (int nt = 0; nt < 8; nt++)
            #pragma unroll
            for (int r = 0; r < 4; r++) c[nt][r] = 0.f;

        #pragma unroll
        for (int ks = 0; ks < 4; ks++) {
            #pragma unroll
            for (int nt = 0; nt < 8; nt++) {
                int bi = (nt * 8 + gr) * PST + ks * 8 + gc;
                uint32_t bh0 = Kh[bi], bh1 = Kh[bi + 4];
                uint32_t bl0 = Kl[bi], bl1 = Kl[bi + 4];
                MMA_BF16(c[nt], qh[ks][0], qh[ks][1], qh[ks][2], qh[ks][3], bl0, bl1);
                MMA_BF16(c[nt], ql[ks][0], ql[ks][1], ql[ks][2], ql[ks][3], bh0, bh1);
                MMA_BF16(c[nt], qh[ks][0], qh[ks][1], qh[ks][2], qh[ks][3], bh0, bh1);
            }
        }

        // ---- mask + scale ----
        const int* mrow0 = mask + (size_t)(q0 + wm + gr) * SS + k0;
        const int* mrow1 = mrow0 + 8 * SS;
        #pragma unroll
        for (int nt = 0; nt < 8; nt++) {
            int col = nt * 8 + 2 * gc;
            int2 mv0 = *(const int2*)(mrow0 + col);
            int2 mv1 = *(const int2*)(mrow1 + col);
            c[nt][0] = mv0.x ? c[nt][0] * scale : -10000.f;
            c[nt][1] = mv0.y ? c[nt][1] * scale : -10000.f;
            c[nt][2] = mv1.x ? c[nt][2] * scale : -10000.f;
            c[nt][3] = mv1.y ? c[nt][3] * scale : -10000.f;
        }

        // ---- online softmax (rows live in quads) ----
        float mx0 = -1e30f, mx1 = -1e30f;
        #pragma unroll
        for (int nt = 0; nt < 8; nt++) {
            mx0 = fmaxf(mx0, fmaxf(c[nt][0], c[nt][1]));
            mx1 = fmaxf(mx1, fmaxf(c[nt][2], c[nt][3]));
        }
        mx0 = fmaxf(mx0, __shfl_xor_sync(0xFFFFFFFF, mx0, 1));
        mx0 = fmaxf(mx0, __shfl_xor_sync(0xFFFFFFFF, mx0, 2));
        mx1 = fmaxf(mx1, __shfl_xor_sync(0xFFFFFFFF, mx1, 1));
        mx1 = fmaxf(mx1, __shfl_xor_sync(0xFFFFFFFF, mx1, 2));

        float mn0 = fmaxf(m0, mx0), mn1 = fmaxf(m1, mx1);
        float al0 = __expf(m0 - mn0), al1 = __expf(m1 - mn1);
        l0 *= al0; l1 *= al1;
        #pragma unroll
        for (int dt = 0; dt < 8; dt++) {
            oacc[dt][0] *= al0; oacc[dt][1] *= al0;
            oacc[dt][2] *= al1; oacc[dt][3] *= al1;
        }

        float s0 = 0.f, s1 = 0.f;
        #pragma unroll
        for (int nt = 0; nt < 8; nt++) {
            c[nt][0] = __expf(c[nt][0] - mn0);
            c[nt][1] = __expf(c[nt][1] - mn0);
            c[nt][2] = __expf(c[nt][2] - mn1);
            c[nt][3] = __expf(c[nt][3] - mn1);
            s0 += c[nt][0] + c[nt][1];
            s1 += c[nt][2] + c[nt][3];
        }
        s0 += __shfl_xor_sync(0xFFFFFFFF, s0, 1);
        s0 += __shfl_xor_sync(0xFFFFFFFF, s0, 2);
        s1 += __shfl_xor_sync(0xFFFFFFFF, s1, 1);
        s1 += __shfl_xor_sync(0xFFFFFFFF, s1, 2);
        l0 += s0; l1 += s1;
        m0 = mn0; m1 = mn1;

        // ---- P @ V : P packed in registers (D-frag == A-frag layout) ----
        #pragma unroll
        for (int ks = 0; ks < 4; ks++) {
            uint32_t pah[4], pal[4];
            bsplit2(c[2*ks][0],   c[2*ks][1],   pah[0], pal[0]);
            bsplit2(c[2*ks][2],   c[2*ks][3],   pah[1], pal[1]);
            bsplit2(c[2*ks+1][0], c[2*ks+1][1], pah[2], pal[2]);
            bsplit2(c[2*ks+1][2], c[2*ks+1][3], pah[3], pal[3]);
            #pragma unroll
            for (int dt = 0; dt < 8; dt++) {
                int bi = (dt * 8 + gr) * PST + ks * 8 + gc;
                uint32_t bh0 = Vh[bi], bh1 = Vh[bi + 4];
                uint32_t bl0 = Vl[bi], bl1 = Vl[bi + 4];
                MMA_BF16(oacc[dt], pah[0], pah[1], pah[2], pah[3], bl0, bl1);
                MMA_BF16(oacc[dt], pal[0], pal[1], pal[2], pal[3], bh0, bh1);
                MMA_BF16(oacc[dt], pah[0], pah[1], pah[2], pah[3], bh0, bh1);
            }
        }
    }

    // ---- normalize + write [B,S,D] ----
    float inv0 = 1.f / l0, inv1 = 1.f / l1;
    float* orow0 = g_attn + ((size_t)b * SS + q0 + wm + gr) * D_MODEL + h * HD;
    float* orow1 = orow0 + 8 * D_MODEL;
    #pragma unroll
    for (int dt = 0; dt < 8; dt++) {
        int col = dt * 8 + 2 * gc;
        *(float2*)(orow0 + col) = make_float2(oacc[dt][0] * inv0, oacc[dt][1] * inv0);
        *(float2*)(orow1 + col) = make_float2(oacc[dt][2] * inv1, oacc[dt][3] * inv1);
    }
}

// ============================================================================
extern "C" void kernel_launch(void* const* d_in, const int* in_sizes, int n_in,
                              void* d_out, int out_size)
{
    const float* q    = (const float*)d_in[0];
    const float* k    = (const float*)d_in[1];
    const float* v    = (const float*)d_in[2];
    const int*   mask = (const int*)  d_in[3];
    const float* wq   = (const float*)d_in[4];
    const float* bq   = (const float*)d_in[5];
    const float* wk   = (const float*)d_in[6];
    const float* bk   = (const float*)d_in[7];
    const float* wv   = (const float*)d_in[8];
    const float* bv   = (const float*)d_in[9];
    const float* wo   = (const float*)d_in[10];
    const float* bo   = (const float*)d_in[11];
    float* out = (float*)d_out;

    dim3 gg(D_MODEL / 128, MROWS / 128);   // (8, 32)
    tc_gemm<<<gg, 256>>>(q, wq, bq, nullptr, 0);
    tc_gemm<<<gg, 256>>>(k, wk, bk, nullptr, 1);
    tc_gemm<<<gg, 256>>>(v, wv, bv, nullptr, 2);
    vtrans_kernel<<<dim3(SS / 64, NH, BB), 128>>>();
    attn_kernel<<<dim3(SS / 64, NH, BB), 128>>>(mask);
    tc_gemm<<<gg, 256>>>(nullptr, wo, bo, out, 3);
}

// round 15
// speedup vs baseline: 1.1111x; 1.0151x over previous
#include <cuda_runtime.h>
#include <cuda_bf16.h>
#include <cstdint>
#include <math.h>

#define D_MODEL 1024
#define NH 16
#define HD 64
#define BB 2
#define SS 2048
#define MROWS (BB*SS)   // 4096
#define NPAIR (MROWS*D_MODEL/2)   // 2M uint32 pairs per tensor

// Scratch (allocation-free __device__ globals)
__device__ uint32_t g_qh[NPAIR], g_ql[NPAIR];     // [B,H,S,Dh/2]
__device__ uint32_t g_kh[NPAIR], g_kl[NPAIR];     // [B,H,S,Dh/2]
__device__ uint32_t g_vth[NPAIR], g_vtl[NPAIR];   // [B,H,Dh,S/2] (V transposed, split)
__device__ float    g_attn[(size_t)MROWS*D_MODEL];// [B,S,D]

// ============================================================================
// helpers
// ============================================================================
__device__ __forceinline__ uint32_t pack_bf2(__nv_bfloat16 a, __nv_bfloat16 b) {
    __nv_bfloat162 v; v.x = a; v.y = b;
    return *(uint32_t*)&v;
}
__device__ __forceinline__ void bsplit2(float x, float y, uint32_t& hi, uint32_t& lo) {
    __nv_bfloat16 hx = __float2bfloat16_rn(x);
    __nv_bfloat16 hy = __float2bfloat16_rn(y);
    __nv_bfloat16 lx = __float2bfloat16_rn(x - __bfloat162float(hx));
    __nv_bfloat16 ly = __float2bfloat16_rn(y - __bfloat162float(hy));
    hi = pack_bf2(hx, hy);
    lo = pack_bf2(lx, ly);
}
__device__ __forceinline__ void bsplit1(float x, __nv_bfloat16& h, __nv_bfloat16& l) {
    h = __float2bfloat16_rn(x);
    l = __float2bfloat16_rn(x - __bfloat162float(h));
}

// mma.sync m16n8k16 bf16: D += A*B (A row-major 16x16, B col-major 16x8)
#define MMA_BF16(dd, a0,a1,a2,a3, b0,b1) \
    asm volatile( \
        "mma.sync.aligned.m16n8k16.row.col.f32.bf16.bf16.f32 " \
        "{%0,%1,%2,%3}, {%4,%5,%6,%7}, {%8,%9}, {%0,%1,%2,%3};" \
        : "+f"((dd)[0]), "+f"((dd)[1]), "+f"((dd)[2]), "+f"((dd)[3]) \
        : "r"(a0), "r"(a1), "r"(a2), "r"(a3), "r"(b0), "r"(b1))

// ============================================================================
// Split-bf16 tensor-core GEMM: C[M,N] = A[M,K] @ W[N,K]^T + bias
// Tile 128x128, K-chunk 32 (2 k16 steps), 3 products (ah*bh + ah*bl + al*bh).
// mode 0/1: write split-bf16 pairs (q/k) in [B,H,S,Dh]
// mode 2:   write split-bf16 V TRANSPOSED in [B,H,Dh,S] (scalar bf16 stores)
// mode 3:   A = g_attn, fp32 out (final O projection)
// ============================================================================
#define GP 18   // pair stride per row (16 + 2 pad)

__global__ __launch_bounds__(256)
void tc_gemm(const float* __restrict__ A, const float* __restrict__ W,
             const float* __restrict__ bias, float* __restrict__ Cout, int mode)
{
    __shared__ uint32_t sh[4 * 128 * GP];   // 36,864 B
    uint32_t* Ah = sh;
    uint32_t* Al = sh + 1 * 128 * GP;
    uint32_t* Bh = sh + 2 * 128 * GP;
    uint32_t* Bl = sh + 3 * 128 * GP;

    const int tid  = threadIdx.x;
    const int wid  = tid >> 5;
    const int lane = tid & 31;
    const int wm   = (wid & 3) << 5;
    const int wn   = (wid >> 2) << 6;
    const int gr   = lane >> 2;
    const int gc   = lane & 3;

    const float* Ap = (mode == 3) ? g_attn : A;
    const int bm = blockIdx.y * 128;
    const int bn = blockIdx.x * 128;

    float acc[2][8][4];
    #pragma unroll
    for (int mt = 0; mt < 2; mt++)
        #pragma unroll
        for (int nt = 0; nt < 8; nt++)
            #pragma unroll
            for (int r = 0; r < 4; r++) acc[mt][nt][r] = 0.f;

    for (int k0 = 0; k0 < D_MODEL; k0 += 32) {
        __syncthreads();
        #pragma unroll
        for (int i = 0; i < 4; i++) {
            int lin = i * 256 + tid;          // 0..1023
            int row = lin >> 3;               // 0..127
            int c4  = (lin & 7) << 2;         // 0..28 (f32 col)
            int so  = row * GP + (c4 >> 1);   // pair index

            float4 a = *(const float4*)(Ap + (size_t)(bm + row) * D_MODEL + k0 + c4);
            uint32_t h0, l0, h1, l1;
            bsplit2(a.x, a.y, h0, l0);
            bsplit2(a.z, a.w, h1, l1);
            *(uint2*)&Ah[so] = make_uint2(h0, h1);
            *(uint2*)&Al[so] = make_uint2(l0, l1);

            float4 b = *(const float4*)(W + (size_t)(bn + row) * D_MODEL + k0 + c4);
            bsplit2(b.x, b.y, h0, l0);
            bsplit2(b.z, b.w, h1, l1);
            *(uint2*)&Bh[so] = make_uint2(h0, h1);
            *(uint2*)&Bl[so] = make_uint2(l0, l1);
        }
        __syncthreads();

        #pragma unroll
        for (int ks = 0; ks < 2; ks++) {
            const int kp = ks * 8 + gc;
            uint32_t ah[2][4], al[2][4];
            #pragma unroll
            for (int mt = 0; mt < 2; mt++) {
                int r0 = (wm + mt * 16 + gr) * GP + kp;
                int r8 = r0 + 8 * GP;
                ah[mt][0] = Ah[r0]; ah[mt][1] = Ah[r8];
                ah[mt][2] = Ah[r0 + 4]; ah[mt][3] = Ah[r8 + 4];
                al[mt][0] = Al[r0]; al[mt][1] = Al[r8];
                al[mt][2] = Al[r0 + 4]; al[mt][3] = Al[r8 + 4];
            }
            #pragma unroll
            for (int nt = 0; nt < 8; nt++) {
                int n0 = (wn + nt * 8 + gr) * GP + kp;
                uint32_t bh0 = Bh[n0], bh1 = Bh[n0 + 4];
                uint32_t bl0 = Bl[n0], bl1 = Bl[n0 + 4];
                #pragma unroll
                for (int mt = 0; mt < 2; mt++) {
                    float* d = acc[mt][nt];
                    MMA_BF16(d, ah[mt][0], ah[mt][1], ah[mt][2], ah[mt][3], bl0, bl1);
                    MMA_BF16(d, al[mt][0], al[mt][1], al[mt][2], al[mt][3], bh0, bh1);
                    MMA_BF16(d, ah[mt][0], ah[mt][1], ah[mt][2], ah[mt][3], bh0, bh1);
                }
            }
        }
    }

    // epilogue
    __nv_bfloat16* vthb = (__nv_bfloat16*)g_vth;
    __nv_bfloat16* vtlb = (__nv_bfloat16*)g_vtl;
    #pragma unroll
    for (int mt = 0; mt < 2; mt++) {
        #pragma unroll
        for (int nt = 0; nt < 8; nt++) {
            int m0 = bm + wm + mt * 16 + gr;
            int n0 = bn + wn + nt * 8 + gc * 2;   // even
            float b0 = bias[n0], b1 = bias[n0 + 1];
            #pragma unroll
            for (int half = 0; half < 2; half++) {
                int m = m0 + half * 8;
                float v0 = acc[mt][nt][half * 2 + 0] + b0;
                float v1 = acc[mt][nt][half * 2 + 1] + b1;
                int b = m >> 11;
                int s = m & (SS - 1);
                int h = n0 >> 6;
                int d = n0 & (HD - 1);
                if (mode <= 1) {
                    size_t pidx = (((size_t)(b * NH + h) * SS + s) * HD + d) >> 1;
                    uint32_t hi, lo;
                    bsplit2(v0, v1, hi, lo);
                    if (mode == 0) { g_qh[pidx] = hi; g_ql[pidx] = lo; }
                    else           { g_kh[pidx] = hi; g_kl[pidx] = lo; }
                } else if (mode == 2) {
                    // transposed split-V: [b,h,d,s] scalar bf16 stores
                    size_t base = ((size_t)(b * NH + h) * HD + d) * SS + s;
                    __nv_bfloat16 hh, ll;
                    bsplit1(v0, hh, ll);
                    vthb[base] = hh; vtlb[base] = ll;
                    bsplit1(v1, hh, ll);
                    vthb[base + SS] = hh; vtlb[base + SS] = ll;
                } else {
                    *(float2*)(Cout + (size_t)m * D_MODEL + n0) = make_float2(v0, v1);
                }
            }
        }
    }
}

// ============================================================================
// Tensor-core flash attention. Block = 128 threads = 4 warps, 64 q rows
// (16/warp), KT=64. All operands pre-split bf16 in gmem; P stays in registers.
// ============================================================================
#define PST 36

__global__ __launch_bounds__(128)
void attn_kernel(const int* __restrict__ mask)
{
    __shared__ uint32_t Kh[64 * PST], Kl[64 * PST], Vh[64 * PST], Vl[64 * PST]; // 36,864 B

    const int t    = threadIdx.x;
    const int wid  = t >> 5;
    const int lane = t & 31;
    const int gr   = lane >> 2;
    const int gc   = lane & 3;
    const int wm   = wid * 16;
    const int q0   = blockIdx.x * 64;
    const int h    = blockIdx.y;
    const int b    = blockIdx.z;
    const float scale = 0.125f;

    const size_t bh = (size_t)(b * NH + h);
    const uint32_t* qhp = g_qh + bh * SS * (HD / 2);
    const uint32_t* qlp = g_ql + bh * SS * (HD / 2);
    const uint32_t* khp = g_kh + bh * SS * (HD / 2);
    const uint32_t* klp = g_kl + bh * SS * (HD / 2);
    const uint32_t* vhp = g_vth + bh * HD * (SS / 2);
    const uint32_t* vlp = g_vtl + bh * HD * (SS / 2);

    uint32_t qh[4][4], ql[4][4];
    {
        int r0 = (q0 + wm + gr) * 32;
        int r1 = r0 + 8 * 32;
        #pragma unroll
        for (int ks = 0; ks < 4; ks++) {
            int p = ks * 8 + gc;
            qh[ks][0] = qhp[r0 + p];     qh[ks][1] = qhp[r1 + p];
            qh[ks][2] = qhp[r0 + p + 4]; qh[ks][3] = qhp[r1 + p + 4];
            ql[ks][0] = qlp[r0 + p];     ql[ks][1] = qlp[r1 + p];
            ql[ks][2] = qlp[r0 + p + 4]; ql[ks][3] = qlp[r1 + p + 4];
        }
    }

    float oacc[8][4];
    #pragma unroll
    for (int dt = 0; dt < 8; dt++)
        #pragma unroll
        for (int r = 0; r < 4; r++) oacc[dt][r] = 0.f;
    float m0 = -1e30f, m1 = -1e30f, l0 = 0.f, l1 = 0.f;

    for (int k0 = 0; k0 < SS; k0 += 64) {
        __syncthreads();

        #pragma unroll
        for (int i = 0; i < 4; i++) {
            int lin = i * 128 + t;
            int row = lin >> 3;
            int c4  = (lin & 7) << 2;
            int so  = row * PST + c4;
            *(uint4*)&Kh[so] = *(const uint4*)(khp + (size_t)(k0 + row) * 32 + c4);
            *(uint4*)&Kl[so] = *(const uint4*)(klp + (size_t)(k0 + row) * 32 + c4);
            *(uint4*)&Vh[so] = *(const uint4*)(vhp + (size_t)row * (SS / 2) + (k0 >> 1) + c4);
            *(uint4*)&Vl[so] = *(const uint4*)(vlp + (size_t)row * (SS / 2) + (k0 >> 1) + c4);
        }
        __syncthreads();

        float c[8][4];
        #pragma unroll
        for (int nt = 0; nt < 8; nt++)
            #pragma unroll
            for (int r = 0; r < 4; r++) c[nt][r] = 0.f;

        #pragma unroll
        for (int ks = 0; ks < 4; ks++) {
            #pragma unroll
            for (int nt = 0; nt < 8; nt++) {
                int bi = (nt * 8 + gr) * PST + ks * 8 + gc;
                uint32_t bh0 = Kh[bi], bh1 = Kh[bi + 4];
                uint32_t bl0 = Kl[bi], bl1 = Kl[bi + 4];
                MMA_BF16(c[nt], qh[ks][0], qh[ks][1], qh[ks][2], qh[ks][3], bl0, bl1);
                MMA_BF16(c[nt], ql[ks][0], ql[ks][1], ql[ks][2], ql[ks][3], bh0, bh1);
                MMA_BF16(c[nt], qh[ks][0], qh[ks][1], qh[ks][2], qh[ks][3], bh0, bh1);
            }
        }

        const int* mrow0 = mask + (size_t)(q0 + wm + gr) * SS + k0;
        const int* mrow1 = mrow0 + 8 * SS;
        #pragma unroll
        for (int nt = 0; nt < 8; nt++) {
            int col = nt * 8 + 2 * gc;
            int2 mv0 = *(const int2*)(mrow0 + col);
            int2 mv1 = *(const int2*)(mrow1 + col);
            c[nt][0] = mv0.x ? c[nt][0] * scale : -10000.f;
            c[nt][1] = mv0.y ? c[nt][1] * scale : -10000.f;
            c[nt][2] = mv1.x ? c[nt][2] * scale : -10000.f;
            c[nt][3] = mv1.y ? c[nt][3] * scale : -10000.f;
        }

        float mx0 = -1e30f, mx1 = -1e30f;
        #pragma unroll
        for (int nt = 0; nt < 8; nt++) {
            mx0 = fmaxf(mx0, fmaxf(c[nt][0], c[nt][1]));
            mx1 = fmaxf(mx1, fmaxf(c[nt][2], c[nt][3]));
        }
        mx0 = fmaxf(mx0, __shfl_xor_sync(0xFFFFFFFF, mx0, 1));
        mx0 = fmaxf(mx0, __shfl_xor_sync(0xFFFFFFFF, mx0, 2));
        mx1 = fmaxf(mx1, __shfl_xor_sync(0xFFFFFFFF, mx1, 1));
        mx1 = fmaxf(mx1, __shfl_xor_sync(0xFFFFFFFF, mx1, 2));

        float mn0 = fmaxf(m0, mx0), mn1 = fmaxf(m1, mx1);
        float al0 = __expf(m0 - mn0), al1 = __expf(m1 - mn1);
        l0 *= al0; l1 *= al1;
        #pragma unroll
        for (int dt = 0; dt < 8; dt++) {
            oacc[dt][0] *= al0; oacc[dt][1] *= al0;
            oacc[dt][2] *= al1; oacc[dt][3] *= al1;
        }

        float s0 = 0.f, s1 = 0.f;
        #pragma unroll
        for (int nt = 0; nt < 8; nt++) {
            c[nt][0] = __expf(c[nt][0] - mn0);
            c[nt][1] = __expf(c[nt][1] - mn0);
            c[nt][2] = __expf(c[nt][2] - mn1);
            c[nt][3] = __expf(c[nt][3] - mn1);
            s0 += c[nt][0] + c[nt][1];
            s1 += c[nt][2] + c[nt][3];
        }
        s0 += __shfl_xor_sync(0xFFFFFFFF, s0, 1);
        s0 += __shfl_xor_sync(0xFFFFFFFF, s0, 2);
        s1 += __shfl_xor_sync(0xFFFFFFFF, s1, 1);
        s1 += __shfl_xor_sync(0xFFFFFFFF, s1, 2);
        l0 += s0; l1 += s1;
        m0 = mn0; m1 = mn1;

        #pragma unroll
        for (int ks = 0; ks < 4; ks++) {
            uint32_t pah[4], pal[4];
            bsplit2(c[2*ks][0],   c[2*ks][1],   pah[0], pal[0]);
            bsplit2(c[2*ks][2],   c[2*ks][3],   pah[1], pal[1]);
            bsplit2(c[2*ks+1][0], c[2*ks+1][1], pah[2], pal[2]);
            bsplit2(c[2*ks+1][2], c[2*ks+1][3], pah[3], pal[3]);
            #pragma unroll
            for (int dt = 0; dt < 8; dt++) {
                int bi = (dt * 8 + gr) * PST + ks * 8 + gc;
                uint32_t bh0 = Vh[bi], bh1 = Vh[bi + 4];
                uint32_t bl0 = Vl[bi], bl1 = Vl[bi + 4];
                MMA_BF16(oacc[dt], pah[0], pah[1], pah[2], pah[3], bl0, bl1);
                MMA_BF16(oacc[dt], pal[0], pal[1], pal[2], pal[3], bh0, bh1);
                MMA_BF16(oacc[dt], pah[0], pah[1], pah[2], pah[3], bh0, bh1);
            }
        }
    }

    float inv0 = 1.f / l0, inv1 = 1.f / l1;
    float* orow0 = g_attn + ((size_t)b * SS + q0 + wm + gr) * D_MODEL + h * HD;
    float* orow1 = orow0 + 8 * D_MODEL;
    #pragma unroll
    for (int dt = 0; dt < 8; dt++) {
        int col = dt * 8 + 2 * gc;
        *(float2*)(orow0 + col) = make_float2(oacc[dt][0] * inv0, oacc[dt][1] * inv0);
        *(float2*)(orow1 + col) = make_float2(oacc[dt][2] * inv1, oacc[dt][3] * inv1);
    }
}

// ============================================================================
extern "C" void kernel_launch(void* const* d_in, const int* in_sizes, int n_in,
                              void* d_out, int out_size)
{
    const float* q    = (const float*)d_in[0];
    const float* k    = (const float*)d_in[1];
    const float* v    = (const float*)d_in[2];
    const int*   mask = (const int*)  d_in[3];
    const float* wq   = (const float*)d_in[4];
    const float* bq   = (const float*)d_in[5];
    const float* wk   = (const float*)d_in[6];
    const float* bk   = (const float*)d_in[7];
    const float* wv   = (const float*)d_in[8];
    const float* bv   = (const float*)d_in[9];
    const float* wo   = (const float*)d_in[10];
    const float* bo   = (const float*)d_in[11];
    float* out = (float*)d_out;

    dim3 gg(D_MODEL / 128, MROWS / 128);   // (8, 32)
    tc_gemm<<<gg, 256>>>(q, wq, bq, nullptr, 0);
    tc_gemm<<<gg, 256>>>(k, wk, bk, nullptr, 1);
    tc_gemm<<<gg, 256>>>(v, wv, bv, nullptr, 2);   // V transposed in-epilogue
    attn_kernel<<<dim3(SS / 64, NH, BB), 128>>>(mask);   // 4th launch -> profiled
    tc_gemm<<<gg, 256>>>(nullptr, wo, bo, out, 3);
}

// round 16
// speedup vs baseline: 1.4137x; 1.2723x over previous
#include <cuda_runtime.h>
#include <cuda_bf16.h>
#include <cstdint>
#include <math.h>

#define D_MODEL 1024
#define NH 16
#define HD 64
#define BB 2
#define SS 2048
#define MROWS (BB*SS)   // 4096
#define NPAIR (MROWS*D_MODEL/2)   // 2M uint32 pairs per tensor

// Scratch (allocation-free __device__ globals)
__device__ uint32_t g_qh[NPAIR], g_ql[NPAIR];     // [B,H,S,Dh/2]
__device__ uint32_t g_kh[NPAIR], g_kl[NPAIR];     // [B,H,S,Dh/2]
__device__ uint32_t g_vth[NPAIR], g_vtl[NPAIR];   // [B,H,Dh,S/2] (V transposed, split)
__device__ float    g_attn[(size_t)MROWS*D_MODEL];// [B,S,D]

// ============================================================================
// helpers
// ============================================================================
__device__ __forceinline__ uint32_t pack_bf2(__nv_bfloat16 a, __nv_bfloat16 b) {
    __nv_bfloat162 v; v.x = a; v.y = b;
    return *(uint32_t*)&v;
}
__device__ __forceinline__ void bsplit2(float x, float y, uint32_t& hi, uint32_t& lo) {
    __nv_bfloat16 hx = __float2bfloat16_rn(x);
    __nv_bfloat16 hy = __float2bfloat16_rn(y);
    __nv_bfloat16 lx = __float2bfloat16_rn(x - __bfloat162float(hx));
    __nv_bfloat16 ly = __float2bfloat16_rn(y - __bfloat162float(hy));
    hi = pack_bf2(hx, hy);
    lo = pack_bf2(lx, ly);
}
__device__ __forceinline__ void bsplit1(float x, __nv_bfloat16& h, __nv_bfloat16& l) {
    h = __float2bfloat16_rn(x);
    l = __float2bfloat16_rn(x - __bfloat162float(h));
}

// mma.sync m16n8k16 bf16: D += A*B (A row-major 16x16, B col-major 16x8)
#define MMA_BF16(dd, a0,a1,a2,a3, b0,b1) \
    asm volatile( \
        "mma.sync.aligned.m16n8k16.row.col.f32.bf16.bf16.f32 " \
        "{%0,%1,%2,%3}, {%4,%5,%6,%7}, {%8,%9}, {%0,%1,%2,%3};" \
        : "+f"((dd)[0]), "+f"((dd)[1]), "+f"((dd)[2]), "+f"((dd)[3]) \
        : "r"(a0), "r"(a1), "r"(a2), "r"(a3), "r"(b0), "r"(b1))

// ============================================================================
// Split-bf16 tensor-core GEMM: C[M,N] = A[M,K] @ W[N,K]^T + bias
// Tile 128x128, K-chunk 32 (2 k16 steps), 3 products (ah*bh + ah*bl + al*bh).
// mode 0/1: write split-bf16 pairs (q/k) in [B,H,S,Dh]
// mode 2:   write split-bf16 V TRANSPOSED in [B,H,Dh,S] (scalar bf16 stores)
// mode 3:   A = g_attn, fp32 out (final O projection)
// ============================================================================
#define GP 18   // pair stride per row (16 + 2 pad)

__global__ __launch_bounds__(256)
void tc_gemm(const float* __restrict__ A, const float* __restrict__ W,
             const float* __restrict__ bias, float* __restrict__ Cout, int mode)
{
    __shared__ uint32_t sh[4 * 128 * GP];   // 36,864 B
    uint32_t* Ah = sh;
    uint32_t* Al = sh + 1 * 128 * GP;
    uint32_t* Bh = sh + 2 * 128 * GP;
    uint32_t* Bl = sh + 3 * 128 * GP;

    const int tid  = threadIdx.x;
    const int wid  = tid >> 5;
    const int lane = tid & 31;
    const int wm   = (wid & 3) << 5;
    const int wn   = (wid >> 2) << 6;
    const int gr   = lane >> 2;
    const int gc   = lane & 3;

    const float* Ap = (mode == 3) ? g_attn : A;
    const int bm = blockIdx.y * 128;
    const int bn = blockIdx.x * 128;

    float acc[2][8][4];
    #pragma unroll
    for (int mt = 0; mt < 2; mt++)
        #pragma unroll
        for (int nt = 0; nt < 8; nt++)
            #pragma unroll
            for (int r = 0; r < 4; r++) acc[mt][nt][r] = 0.f;

    for (int k0 = 0; k0 < D_MODEL; k0 += 32) {
        __syncthreads();
        #pragma unroll
        for (int i = 0; i < 4; i++) {
            int lin = i * 256 + tid;          // 0..1023
            int row = lin >> 3;               // 0..127
            int c4  = (lin & 7) << 2;         // 0..28 (f32 col)
            int so  = row * GP + (c4 >> 1);   // pair index

            float4 a = *(const float4*)(Ap + (size_t)(bm + row) * D_MODEL + k0 + c4);
            uint32_t h0, l0, h1, l1;
            bsplit2(a.x, a.y, h0, l0);
            bsplit2(a.z, a.w, h1, l1);
            *(uint2*)&Ah[so] = make_uint2(h0, h1);
            *(uint2*)&Al[so] = make_uint2(l0, l1);

            float4 b = *(const float4*)(W + (size_t)(bn + row) * D_MODEL + k0 + c4);
            bsplit2(b.x, b.y, h0, l0);
            bsplit2(b.z, b.w, h1, l1);
            *(uint2*)&Bh[so] = make_uint2(h0, h1);
            *(uint2*)&Bl[so] = make_uint2(l0, l1);
        }
        __syncthreads();

        #pragma unroll
        for (int ks = 0; ks < 2; ks++) {
            const int kp = ks * 8 + gc;
            uint32_t ah[2][4], al[2][4];
            #pragma unroll
            for (int mt = 0; mt < 2; mt++) {
                int r0 = (wm + mt * 16 + gr) * GP + kp;
                int r8 = r0 + 8 * GP;
                ah[mt][0] = Ah[r0]; ah[mt][1] = Ah[r8];
                ah[mt][2] = Ah[r0 + 4]; ah[mt][3] = Ah[r8 + 4];
                al[mt][0] = Al[r0]; al[mt][1] = Al[r8];
                al[mt][2] = Al[r0 + 4]; al[mt][3] = Al[r8 + 4];
            }
            #pragma unroll
            for (int nt = 0; nt < 8; nt++) {
                int n0 = (wn + nt * 8 + gr) * GP + kp;
                uint32_t bh0 = Bh[n0], bh1 = Bh[n0 + 4];
                uint32_t bl0 = Bl[n0], bl1 = Bl[n0 + 4];
                #pragma unroll
                for (int mt = 0; mt < 2; mt++) {
                    float* d = acc[mt][nt];
                    MMA_BF16(d, ah[mt][0], ah[mt][1], ah[mt][2], ah[mt][3], bl0, bl1);
                    MMA_BF16(d, al[mt][0], al[mt][1], al[mt][2], al[mt][3], bh0, bh1);
                    MMA_BF16(d, ah[mt][0], ah[mt][1], ah[mt][2], ah[mt][3], bh0, bh1);
                }
            }
        }
    }

    // epilogue
    __nv_bfloat16* vthb = (__nv_bfloat16*)g_vth;
    __nv_bfloat16* vtlb = (__nv_bfloat16*)g_vtl;
    #pragma unroll
    for (int mt = 0; mt < 2; mt++) {
        #pragma unroll
        for (int nt = 0; nt < 8; nt++) {
            int m0 = bm + wm + mt * 16 + gr;
            int n0 = bn + wn + nt * 8 + gc * 2;   // even
            float b0 = bias[n0], b1 = bias[n0 + 1];
            #pragma unroll
            for (int half = 0; half < 2; half++) {
                int m = m0 + half * 8;
                float v0 = acc[mt][nt][half * 2 + 0] + b0;
                float v1 = acc[mt][nt][half * 2 + 1] + b1;
                int b = m >> 11;
                int s = m & (SS - 1);
                int h = n0 >> 6;
                int d = n0 & (HD - 1);
                if (mode <= 1) {
                    size_t pidx = (((size_t)(b * NH + h) * SS + s) * HD + d) >> 1;
                    uint32_t hi, lo;
                    bsplit2(v0, v1, hi, lo);
                    if (mode == 0) { g_qh[pidx] = hi; g_ql[pidx] = lo; }
                    else           { g_kh[pidx] = hi; g_kl[pidx] = lo; }
                } else if (mode == 2) {
                    size_t base = ((size_t)(b * NH + h) * HD + d) * SS + s;
                    __nv_bfloat16 hh, ll;
                    bsplit1(v0, hh, ll);
                    vthb[base] = hh; vtlb[base] = ll;
                    bsplit1(v1, hh, ll);
                    vthb[base + SS] = hh; vtlb[base + SS] = ll;
                } else {
                    *(float2*)(Cout + (size_t)m * D_MODEL + n0) = make_float2(v0, v1);
                }
            }
        }
    }
}

// ============================================================================
// Tensor-core flash attention. Block = 128 threads = 4 warps, 64 q rows
// (16/warp), KT=64. __launch_bounds__(128, 3): cap ~170 regs -> 3 CTAs/SM
// (was 176 regs = 2 CTAs; occ 12%, issue 20.5% — latency-bound on 2 warps/SMSP).
// ============================================================================
#define PST 36

__global__ __launch_bounds__(128, 3)
void attn_kernel(const int* __restrict__ mask)
{
    __shared__ uint32_t Kh[64 * PST], Kl[64 * PST], Vh[64 * PST], Vl[64 * PST]; // 36,864 B

    const int t    = threadIdx.x;
    const int wid  = t >> 5;
    const int lane = t & 31;
    const int gr   = lane >> 2;
    const int gc   = lane & 3;
    const int wm   = wid * 16;
    const int q0   = blockIdx.x * 64;
    const int h    = blockIdx.y;
    const int b    = blockIdx.z;
    const float scale = 0.125f;

    const size_t bh = (size_t)(b * NH + h);
    const uint32_t* qhp = g_qh + bh * SS * (HD / 2);
    const uint32_t* qlp = g_ql + bh * SS * (HD / 2);
    const uint32_t* khp = g_kh + bh * SS * (HD / 2);
    const uint32_t* klp = g_kl + bh * SS * (HD / 2);
    const uint32_t* vhp = g_vth + bh * HD * (SS / 2);
    const uint32_t* vlp = g_vtl + bh * HD * (SS / 2);

    uint32_t qh[4][4], ql[4][4];
    {
        int r0 = (q0 + wm + gr) * 32;
        int r1 = r0 + 8 * 32;
        #pragma unroll
        for (int ks = 0; ks < 4; ks++) {
            int p = ks * 8 + gc;
            qh[ks][0] = qhp[r0 + p];     qh[ks][1] = qhp[r1 + p];
            qh[ks][2] = qhp[r0 + p + 4]; qh[ks][3] = qhp[r1 + p + 4];
            ql[ks][0] = qlp[r0 + p];     ql[ks][1] = qlp[r1 + p];
            ql[ks][2] = qlp[r0 + p + 4]; ql[ks][3] = qlp[r1 + p + 4];
        }
    }

    float oacc[8][4];
    #pragma unroll
    for (int dt = 0; dt < 8; dt++)
        #pragma unroll
        for (int r = 0; r < 4; r++) oacc[dt][r] = 0.f;
    float m0 = -1e30f, m1 = -1e30f, l0 = 0.f, l1 = 0.f;

    for (int k0 = 0; k0 < SS; k0 += 64) {
        __syncthreads();

        #pragma unroll
        for (int i = 0; i < 4; i++) {
            int lin = i * 128 + t;
            int row = lin >> 3;
            int c4  = (lin & 7) << 2;
            int so  = row * PST + c4;
            *(uint4*)&Kh[so] = *(const uint4*)(khp + (size_t)(k0 + row) * 32 + c4);
            *(uint4*)&Kl[so] = *(const uint4*)(klp + (size_t)(k0 + row) * 32 + c4);
            *(uint4*)&Vh[so] = *(const uint4*)(vhp + (size_t)row * (SS / 2) + (k0 >> 1) + c4);
            *(uint4*)&Vl[so] = *(const uint4*)(vlp + (size_t)row * (SS / 2) + (k0 >> 1) + c4);
        }
        __syncthreads();

        float c[8][4];
        #pragma unroll
        for (int nt = 0; nt < 8; nt++)
            #pragma unroll
            for (int r = 0; r < 4; r++) c[nt][r] = 0.f;

        #pragma unroll
        for (int ks = 0; ks < 4; ks++) {
            #pragma unroll
            for (int nt = 0; nt < 8; nt++) {
                int bi = (nt * 8 + gr) * PST + ks * 8 + gc;
                uint32_t bh0 = Kh[bi], bh1 = Kh[bi + 4];
                uint32_t bl0 = Kl[bi], bl1 = Kl[bi + 4];
                MMA_BF16(c[nt], qh[ks][0], qh[ks][1], qh[ks][2], qh[ks][3], bl0, bl1);
                MMA_BF16(c[nt], ql[ks][0], ql[ks][1], ql[ks][2], ql[ks][3], bh0, bh1);
                MMA_BF16(c[nt], qh[ks][0], qh[ks][1], qh[ks][2], qh[ks][3], bh0, bh1);
            }
        }

        const int* mrow0 = mask + (size_t)(q0 + wm + gr) * SS + k0;
        const int* mrow1 = mrow0 + 8 * SS;
        #pragma unroll
        for (int nt = 0; nt < 8; nt++) {
            int col = nt * 8 + 2 * gc;
            int2 mv0 = *(const int2*)(mrow0 + col);
            int2 mv1 = *(const int2*)(mrow1 + col);
            c[nt][0] = mv0.x ? c[nt][0] * scale : -10000.f;
            c[nt][1] = mv0.y ? c[nt][1] * scale : -10000.f;
            c[nt][2] = mv1.x ? c[nt][2] * scale : -10000.f;
            c[nt][3] = mv1.y ? c[nt][3] * scale : -10000.f;
        }

        float mx0 = -1e30f, mx1 = -1e30f;
        #pragma unroll
        for (int nt = 0; nt < 8; nt++) {
            mx0 = fmaxf(mx0, fmaxf(c[nt][0], c[nt][1]));
            mx1 = fmaxf(mx1, fmaxf(c[nt][2], c[nt][3]));
        }
        mx0 = fmaxf(mx0, __shfl_xor_sync(0xFFFFFFFF, mx0, 1));
        mx0 = fmaxf(mx0, __shfl_xor_sync(0xFFFFFFFF, mx0, 2));
        mx1 = fmaxf(mx1, __shfl_xor_sync(0xFFFFFFFF, mx1, 1));
        mx1 = fmaxf(mx1, __shfl_xor_sync(0xFFFFFFFF, mx1, 2));

        float mn0 = fmaxf(m0, mx0), mn1 = fmaxf(m1, mx1);
        float al0 = __expf(m0 - mn0), al1 = __expf(m1 - mn1);
        l0 *= al0; l1 *= al1;
        #pragma unroll
        for (int dt = 0; dt < 8; dt++) {
            oacc[dt][0] *= al0; oacc[dt][1] *= al0;
            oacc[dt][2] *= al1; oacc[dt][3] *= al1;
        }

        float s0 = 0.f, s1 = 0.f;
        #pragma unroll
        for (int nt = 0; nt < 8; nt++) {
            c[nt][0] = __expf(c[nt][0] - mn0);
            c[nt][1] = __expf(c[nt][1] - mn0);
            c[nt][2] = __expf(c[nt][2] - mn1);
            c[nt][3] = __expf(c[nt][3] - mn1);
            s0 += c[nt][0] + c[nt][1];
            s1 += c[nt][2] + c[nt][3];
        }
        s0 += __shfl_xor_sync(0xFFFFFFFF, s0, 1);
        s0 += __shfl_xor_sync(0xFFFFFFFF, s0, 2);
        s1 += __shfl_xor_sync(0xFFFFFFFF, s1, 1);
        s1 += __shfl_xor_sync(0xFFFFFFFF, s1, 2);
        l0 += s0; l1 += s1;
        m0 = mn0; m1 = mn1;

        #pragma unroll
        for (int ks = 0; ks < 4; ks++) {
            uint32_t pah[4], pal[4];
            bsplit2(c[2*ks][0],   c[2*ks][1],   pah[0], pal[0]);
            bsplit2(c[2*ks][2],   c[2*ks][3],   pah[1], pal[1]);
            bsplit2(c[2*ks+1][0], c[2*ks+1][1], pah[2], pal[2]);
            bsplit2(c[2*ks+1][2], c[2*ks+1][3], pah[3], pal[3]);
            #pragma unroll
            for (int dt = 0; dt < 8; dt++) {
                int bi = (dt * 8 + gr) * PST + ks * 8 + gc;
                uint32_t bh0 = Vh[bi], bh1 = Vh[bi + 4];
                uint32_t bl0 = Vl[bi], bl1 = Vl[bi + 4];
                MMA_BF16(oacc[dt], pah[0], pah[1], pah[2], pah[3], bl0, bl1);
                MMA_BF16(oacc[dt], pal[0], pal[1], pal[2], pal[3], bh0, bh1);
                MMA_BF16(oacc[dt], pah[0], pah[1], pah[2], pah[3], bh0, bh1);
            }
        }
    }

    float inv0 = 1.f / l0, inv1 = 1.f / l1;
    float* orow0 = g_attn + ((size_t)b * SS + q0 + wm + gr) * D_MODEL + h * HD;
    float* orow1 = orow0 + 8 * D_MODEL;
    #pragma unroll
    for (int dt = 0; dt < 8; dt++) {
        int col = dt * 8 + 2 * gc;
        *(float2*)(orow0 + col) = make_float2(oacc[dt][0] * inv0, oacc[dt][1] * inv0);
        *(float2*)(orow1 + col) = make_float2(oacc[dt][2] * inv1, oacc[dt][3] * inv1);
    }
}

// ============================================================================
extern "C" void kernel_launch(void* const* d_in, const int* in_sizes, int n_in,
                              void* d_out, int out_size)
{
    const float* q    = (const float*)d_in[0];
    const float* k    = (const float*)d_in[1];
    const float* v    = (const float*)d_in[2];
    const int*   mask = (const int*)  d_in[3];
    const float* wq   = (const float*)d_in[4];
    const float* bq   = (const float*)d_in[5];
    const float* wk   = (const float*)d_in[6];
    const float* bk   = (const float*)d_in[7];
    const float* wv   = (const float*)d_in[8];
    const float* bv   = (const float*)d_in[9];
    const float* wo   = (const float*)d_in[10];
    const float* bo   = (const float*)d_in[11];
    float* out = (float*)d_out;

    dim3 gg(D_MODEL / 128, MROWS / 128);   // (8, 32)
    tc_gemm<<<gg, 256>>>(q, wq, bq, nullptr, 0);
    tc_gemm<<<gg, 256>>>(k, wk, bk, nullptr, 1);
    tc_gemm<<<gg, 256>>>(v, wv, bv, nullptr, 2);   // V transposed in-epilogue
    attn_kernel<<<dim3(SS / 64, NH, BB), 128>>>(mask);   // 4th launch -> profiled
    tc_gemm<<<gg, 256>>>(nullptr, wo, bo, out, 3);
}

// round 17
// speedup vs baseline: 1.5286x; 1.0813x over previous
#include <cuda_runtime.h>
#include <cuda_bf16.h>
#include <cstdint>
#include <math.h>

#define D_MODEL 1024
#define NH 16
#define HD 64
#define BB 2
#define SS 2048
#define MROWS (BB*SS)   // 4096
#define NPAIR (MROWS*D_MODEL/2)   // 2M uint32 pairs per tensor

// Scratch (allocation-free __device__ globals)
__device__ uint32_t g_qh[NPAIR], g_ql[NPAIR];     // [B,H,S,Dh/2]
__device__ uint32_t g_kh[NPAIR], g_kl[NPAIR];     // [B,H,S,Dh/2]
__device__ uint32_t g_vth[NPAIR], g_vtl[NPAIR];   // [B,H,Dh,S/2] (V transposed, split)
__device__ float    g_attn[(size_t)MROWS*D_MODEL];// [B,S,D]

// ============================================================================
// helpers
// ============================================================================
__device__ __forceinline__ uint32_t smem_u32(const void* p) {
    uint32_t a;
    asm("{ .reg .u64 t; cvta.to.shared.u64 t, %1; cvt.u32.u64 %0, t; }" : "=r"(a) : "l"(p));
    return a;
}
__device__ __forceinline__ uint32_t pack_bf2(__nv_bfloat16 a, __nv_bfloat16 b) {
    __nv_bfloat162 v; v.x = a; v.y = b;
    return *(uint32_t*)&v;
}
__device__ __forceinline__ void bsplit2(float x, float y, uint32_t& hi, uint32_t& lo) {
    __nv_bfloat16 hx = __float2bfloat16_rn(x);
    __nv_bfloat16 hy = __float2bfloat16_rn(y);
    __nv_bfloat16 lx = __float2bfloat16_rn(x - __bfloat162float(hx));
    __nv_bfloat16 ly = __float2bfloat16_rn(y - __bfloat162float(hy));
    hi = pack_bf2(hx, hy);
    lo = pack_bf2(lx, ly);
}
__device__ __forceinline__ void bsplit1(float x, __nv_bfloat16& h, __nv_bfloat16& l) {
    h = __float2bfloat16_rn(x);
    l = __float2bfloat16_rn(x - __bfloat162float(h));
}

// mma.sync m16n8k16 bf16: D += A*B (A row-major 16x16, B col-major 16x8)
#define MMA_BF16(dd, a0,a1,a2,a3, b0,b1) \
    asm volatile( \
        "mma.sync.aligned.m16n8k16.row.col.f32.bf16.bf16.f32 " \
        "{%0,%1,%2,%3}, {%4,%5,%6,%7}, {%8,%9}, {%0,%1,%2,%3};" \
        : "+f"((dd)[0]), "+f"((dd)[1]), "+f"((dd)[2]), "+f"((dd)[3]) \
        : "r"(a0), "r"(a1), "r"(a2), "r"(a3), "r"(b0), "r"(b1))

// ldmatrix x4: four 8x8 b16 matrices; thread l supplies row address for matrix l>>3
#define LDSM_X4(r0,r1,r2,r3, addr) \
    asm volatile("ldmatrix.sync.aligned.m8n8.x4.shared.b16 {%0,%1,%2,%3}, [%4];" \
                 : "=r"(r0), "=r"(r1), "=r"(r2), "=r"(r3) : "r"(addr))

// ============================================================================
// Split-bf16 tensor-core GEMM (unchanged from R16)
// ============================================================================
#define GP 18   // pair stride per row (16 + 2 pad)

__global__ __launch_bounds__(256)
void tc_gemm(const float* __restrict__ A, const float* __restrict__ W,
             const float* __restrict__ bias, float* __restrict__ Cout, int mode)
{
    __shared__ uint32_t sh[4 * 128 * GP];   // 36,864 B
    uint32_t* Ah = sh;
    uint32_t* Al = sh + 1 * 128 * GP;
    uint32_t* Bh = sh + 2 * 128 * GP;
    uint32_t* Bl = sh + 3 * 128 * GP;

    const int tid  = threadIdx.x;
    const int wid  = tid >> 5;
    const int lane = tid & 31;
    const int wm   = (wid & 3) << 5;
    const int wn   = (wid >> 2) << 6;
    const int gr   = lane >> 2;
    const int gc   = lane & 3;

    const float* Ap = (mode == 3) ? g_attn : A;
    const int bm = blockIdx.y * 128;
    const int bn = blockIdx.x * 128;

    float acc[2][8][4];
    #pragma unroll
    for (int mt = 0; mt < 2; mt++)
        #pragma unroll
        for (int nt = 0; nt < 8; nt++)
            #pragma unroll
            for (int r = 0; r < 4; r++) acc[mt][nt][r] = 0.f;

    for (int k0 = 0; k0 < D_MODEL; k0 += 32) {
        __syncthreads();
        #pragma unroll
        for (int i = 0; i < 4; i++) {
            int lin = i * 256 + tid;          // 0..1023
            int row = lin >> 3;               // 0..127
            int c4  = (lin & 7) << 2;         // 0..28 (f32 col)
            int so  = row * GP + (c4 >> 1);   // pair index

            float4 a = *(const float4*)(Ap + (size_t)(bm + row) * D_MODEL + k0 + c4);
            uint32_t h0, l0, h1, l1;
            bsplit2(a.x, a.y, h0, l0);
            bsplit2(a.z, a.w, h1, l1);
            *(uint2*)&Ah[so] = make_uint2(h0, h1);
            *(uint2*)&Al[so] = make_uint2(l0, l1);

            float4 b = *(const float4*)(W + (size_t)(bn + row) * D_MODEL + k0 + c4);
            bsplit2(b.x, b.y, h0, l0);
            bsplit2(b.z, b.w, h1, l1);
            *(uint2*)&Bh[so] = make_uint2(h0, h1);
            *(uint2*)&Bl[so] = make_uint2(l0, l1);
        }
        __syncthreads();

        #pragma unroll
        for (int ks = 0; ks < 2; ks++) {
            const int kp = ks * 8 + gc;
            uint32_t ah[2][4], al[2][4];
            #pragma unroll
            for (int mt = 0; mt < 2; mt++) {
                int r0 = (wm + mt * 16 + gr) * GP + kp;
                int r8 = r0 + 8 * GP;
                ah[mt][0] = Ah[r0]; ah[mt][1] = Ah[r8];
                ah[mt][2] = Ah[r0 + 4]; ah[mt][3] = Ah[r8 + 4];
                al[mt][0] = Al[r0]; al[mt][1] = Al[r8];
                al[mt][2] = Al[r0 + 4]; al[mt][3] = Al[r8 + 4];
            }
            #pragma unroll
            for (int nt = 0; nt < 8; nt++) {
                int n0 = (wn + nt * 8 + gr) * GP + kp;
                uint32_t bh0 = Bh[n0], bh1 = Bh[n0 + 4];
                uint32_t bl0 = Bl[n0], bl1 = Bl[n0 + 4];
                #pragma unroll
                for (int mt = 0; mt < 2; mt++) {
                    float* d = acc[mt][nt];
                    MMA_BF16(d, ah[mt][0], ah[mt][1], ah[mt][2], ah[mt][3], bl0, bl1);
                    MMA_BF16(d, al[mt][0], al[mt][1], al[mt][2], al[mt][3], bh0, bh1);
                    MMA_BF16(d, ah[mt][0], ah[mt][1], ah[mt][2], ah[mt][3], bh0, bh1);
                }
            }
        }
    }

    // epilogue
    __nv_bfloat16* vthb = (__nv_bfloat16*)g_vth;
    __nv_bfloat16* vtlb = (__nv_bfloat16*)g_vtl;
    #pragma unroll
    for (int mt = 0; mt < 2; mt++) {
        #pragma unroll
        for (int nt = 0; nt < 8; nt++) {
            int m0 = bm + wm + mt * 16 + gr;
            int n0 = bn + wn + nt * 8 + gc * 2;   // even
            float b0 = bias[n0], b1 = bias[n0 + 1];
            #pragma unroll
            for (int half = 0; half < 2; half++) {
                int m = m0 + half * 8;
                float v0 = acc[mt][nt][half * 2 + 0] + b0;
                float v1 = acc[mt][nt][half * 2 + 1] + b1;
                int b = m >> 11;
                int s = m & (SS - 1);
                int h = n0 >> 6;
                int d = n0 & (HD - 1);
                if (mode <= 1) {
                    size_t pidx = (((size_t)(b * NH + h) * SS + s) * HD + d) >> 1;
                    uint32_t hi, lo;
                    bsplit2(v0, v1, hi, lo);
                    if (mode == 0) { g_qh[pidx] = hi; g_ql[pidx] = lo; }
                    else           { g_kh[pidx] = hi; g_kl[pidx] = lo; }
                } else if (mode == 2) {
                    size_t base = ((size_t)(b * NH + h) * HD + d) * SS + s;
                    __nv_bfloat16 hh, ll;
                    bsplit1(v0, hh, ll);
                    vthb[base] = hh; vtlb[base] = ll;
                    bsplit1(v1, hh, ll);
                    vthb[base + SS] = hh; vtlb[base + SS] = ll;
                } else {
                    *(float2*)(Cout + (size_t)m * D_MODEL + n0) = make_float2(v0, v1);
                }
            }
        }
    }
}

// ============================================================================
// Tensor-core flash attention. 128 threads = 4 warps, 64 q rows, KT=64.
// __launch_bounds__(128, 3): 3 CTAs/SM (R16 win). Fragment loads via
// ldmatrix.m8n8.x4: one instr loads {(nt,b0),(nt,b1),(nt+1,b0),(nt+1,b1)}
// (thread l -> row l>>2, pair l&3 matches mma B-fragment; conflict-free at
// PST=36: 8 rows hit banks 4r mod 32, 4 words each = all 32 banks once).
// ============================================================================
#define PST 36

__global__ __launch_bounds__(128, 3)
void attn_kernel(const int* __restrict__ mask)
{
    __shared__ uint32_t Kh[64 * PST], Kl[64 * PST], Vh[64 * PST], Vl[64 * PST]; // 36,864 B

    const int t    = threadIdx.x;
    const int wid  = t >> 5;
    const int lane = t & 31;
    const int gr   = lane >> 2;
    const int gc   = lane & 3;
    const int wm   = wid * 16;
    const int q0   = blockIdx.x * 64;
    const int h    = blockIdx.y;
    const int b    = blockIdx.z;
    const float scale = 0.125f;

    // ldmatrix per-lane address components: matrix l>>3 of 4
    //   row-in-16-block = ((lane>>4)&1)*8 + (lane&7), col4 = ((lane>>3)&1)*4
    const int lmRow  = ((lane >> 4) & 1) * 8 + (lane & 7);
    const int lmCol4 = ((lane >> 3) & 1) * 4;
    const uint32_t sKh = smem_u32(Kh), sKl = smem_u32(Kl);
    const uint32_t sVh = smem_u32(Vh), sVl = smem_u32(Vl);

    const size_t bh = (size_t)(b * NH + h);
    const uint32_t* qhp = g_qh + bh * SS * (HD / 2);
    const uint32_t* qlp = g_ql + bh * SS * (HD / 2);
    const uint32_t* khp = g_kh + bh * SS * (HD / 2);
    const uint32_t* klp = g_kl + bh * SS * (HD / 2);
    const uint32_t* vhp = g_vth + bh * HD * (SS / 2);
    const uint32_t* vlp = g_vtl + bh * HD * (SS / 2);

    uint32_t qh[4][4], ql[4][4];
    {
        int r0 = (q0 + wm + gr) * 32;
        int r1 = r0 + 8 * 32;
        #pragma unroll
        for (int ks = 0; ks < 4; ks++) {
            int p = ks * 8 + gc;
            qh[ks][0] = qhp[r0 + p];     qh[ks][1] = qhp[r1 + p];
            qh[ks][2] = qhp[r0 + p + 4]; qh[ks][3] = qhp[r1 + p + 4];
            ql[ks][0] = qlp[r0 + p];     ql[ks][1] = qlp[r1 + p];
            ql[ks][2] = qlp[r0 + p + 4]; ql[ks][3] = qlp[r1 + p + 4];
        }
    }

    float oacc[8][4];
    #pragma unroll
    for (int dt = 0; dt < 8; dt++)
        #pragma unroll
        for (int r = 0; r < 4; r++) oacc[dt][r] = 0.f;
    float m0 = -1e30f, m1 = -1e30f, l0 = 0.f, l1 = 0.f;

    for (int k0 = 0; k0 < SS; k0 += 64) {
        __syncthreads();

        #pragma unroll
        for (int i = 0; i < 4; i++) {
            int lin = i * 128 + t;
            int row = lin >> 3;
            int c4  = (lin & 7) << 2;
            int so  = row * PST + c4;
            *(uint4*)&Kh[so] = *(const uint4*)(khp + (size_t)(k0 + row) * 32 + c4);
            *(uint4*)&Kl[so] = *(const uint4*)(klp + (size_t)(k0 + row) * 32 + c4);
            *(uint4*)&Vh[so] = *(const uint4*)(vhp + (size_t)row * (SS / 2) + (k0 >> 1) + c4);
            *(uint4*)&Vl[so] = *(const uint4*)(vlp + (size_t)row * (SS / 2) + (k0 >> 1) + c4);
        }
        __syncthreads();

        // ---- QK^T (ldmatrix x4 fragment loads) ----
        float c[8][4];
        #pragma unroll
        for (int nt = 0; nt < 8; nt++)
            #pragma unroll
            for (int r = 0; r < 4; r++) c[nt][r] = 0.f;

        #pragma unroll
        for (int ks = 0; ks < 4; ks++) {
            #pragma unroll
            for (int ntp = 0; ntp < 4; ntp++) {
                uint32_t off = (uint32_t)(((ntp * 16 + lmRow) * PST + ks * 8 + lmCol4) * 4);
                uint32_t h0, h1, h2, h3, l0w, l1w, l2w, l3w;
                LDSM_X4(h0, h1, h2, h3, sKh + off);
                LDSM_X4(l0w, l1w, l2w, l3w, sKl + off);
                float* d0 = c[2 * ntp];
                float* d1 = c[2 * ntp + 1];
                MMA_BF16(d0, qh[ks][0], qh[ks][1], qh[ks][2], qh[ks][3], l0w, l1w);
                MMA_BF16(d0, ql[ks][0], ql[ks][1], ql[ks][2], ql[ks][3], h0, h1);
                MMA_BF16(d0, qh[ks][0], qh[ks][1], qh[ks][2], qh[ks][3], h0, h1);
                MMA_BF16(d1, qh[ks][0], qh[ks][1], qh[ks][2], qh[ks][3], l2w, l3w);
                MMA_BF16(d1, ql[ks][0], ql[ks][1], ql[ks][2], ql[ks][3], h2, h3);
                MMA_BF16(d1, qh[ks][0], qh[ks][1], qh[ks][2], qh[ks][3], h2, h3);
            }
        }

        // ---- mask + scale ----
        const int* mrow0 = mask + (size_t)(q0 + wm + gr) * SS + k0;
        const int* mrow1 = mrow0 + 8 * SS;
        #pragma unroll
        for (int nt = 0; nt < 8; nt++) {
            int col = nt * 8 + 2 * gc;
            int2 mv0 = *(const int2*)(mrow0 + col);
            int2 mv1 = *(const int2*)(mrow1 + col);
            c[nt][0] = mv0.x ? c[nt][0] * scale : -10000.f;
            c[nt][1] = mv0.y ? c[nt][1] * scale : -10000.f;
            c[nt][2] = mv1.x ? c[nt][2] * scale : -10000.f;
            c[nt][3] = mv1.y ? c[nt][3] * scale : -10000.f;
        }

        // ---- online softmax (rows in quads) ----
        float mx0 = -1e30f, mx1 = -1e30f;
        #pragma unroll
        for (int nt = 0; nt < 8; nt++) {
            mx0 = fmaxf(mx0, fmaxf(c[nt][0], c[nt][1]));
            mx1 = fmaxf(mx1, fmaxf(c[nt][2], c[nt][3]));
        }
        mx0 = fmaxf(mx0, __shfl_xor_sync(0xFFFFFFFF, mx0, 1));
        mx0 = fmaxf(mx0, __shfl_xor_sync(0xFFFFFFFF, mx0, 2));
        mx1 = fmaxf(mx1, __shfl_xor_sync(0xFFFFFFFF, mx1, 1));
        mx1 = fmaxf(mx1, __shfl_xor_sync(0xFFFFFFFF, mx1, 2));

        float mn0 = fmaxf(m0, mx0), mn1 = fmaxf(m1, mx1);
        float al0 = __expf(m0 - mn0), al1 = __expf(m1 - mn1);
        l0 *= al0; l1 *= al1;
        #pragma unroll
        for (int dt = 0; dt < 8; dt++) {
            oacc[dt][0] *= al0; oacc[dt][1] *= al0;
            oacc[dt][2] *= al1; oacc[dt][3] *= al1;
        }

        float s0 = 0.f, s1 = 0.f;
        #pragma unroll
        for (int nt = 0; nt < 8; nt++) {
            c[nt][0] = __expf(c[nt][0] - mn0);
            c[nt][1] = __expf(c[nt][1] - mn0);
            c[nt][2] = __expf(c[nt][2] - mn1);
            c[nt][3] = __expf(c[nt][3] - mn1);
            s0 += c[nt][0] + c[nt][1];
            s1 += c[nt][2] + c[nt][3];
        }
        s0 += __shfl_xor_sync(0xFFFFFFFF, s0, 1);
        s0 += __shfl_xor_sync(0xFFFFFFFF, s0, 2);
        s1 += __shfl_xor_sync(0xFFFFFFFF, s1, 1);
        s1 += __shfl_xor_sync(0xFFFFFFFF, s1, 2);
        l0 += s0; l1 += s1;
        m0 = mn0; m1 = mn1;

        // ---- P @ V (ldmatrix x4 fragment loads) ----
        #pragma unroll
        for (int ks = 0; ks < 4; ks++) {
            uint32_t pah[4], pal[4];
            bsplit2(c[2*ks][0],   c[2*ks][1],   pah[0], pal[0]);
            bsplit2(c[2*ks][2],   c[2*ks][3],   pah[1], pal[1]);
            bsplit2(c[2*ks+1][0], c[2*ks+1][1], pah[2], pal[2]);
            bsplit2(c[2*ks+1][2], c[2*ks+1][3], pah[3], pal[3]);
            #pragma unroll
            for (int dtp = 0; dtp < 4; dtp++) {
                uint32_t off = (uint32_t)(((dtp * 16 + lmRow) * PST + ks * 8 + lmCol4) * 4);
                uint32_t h0, h1, h2, h3, l0w, l1w, l2w, l3w;
                LDSM_X4(h0, h1, h2, h3, sVh + off);
                LDSM_X4(l0w, l1w, l2w, l3w, sVl + off);
                float* d0 = oacc[2 * dtp];
                float* d1 = oacc[2 * dtp + 1];
                MMA_BF16(d0, pah[0], pah[1], pah[2], pah[3], l0w, l1w);
                MMA_BF16(d0, pal[0], pal[1], pal[2], pal[3], h0, h1);
                MMA_BF16(d0, pah[0], pah[1], pah[2], pah[3], h0, h1);
                MMA_BF16(d1, pah[0], pah[1], pah[2], pah[3], l2w, l3w);
                MMA_BF16(d1, pal[0], pal[1], pal[2], pal[3], h2, h3);
                MMA_BF16(d1, pah[0], pah[1], pah[2], pah[3], h2, h3);
            }
        }
    }

    float inv0 = 1.f / l0, inv1 = 1.f / l1;
    float* orow0 = g_attn + ((size_t)b * SS + q0 + wm + gr) * D_MODEL + h * HD;
    float* orow1 = orow0 + 8 * D_MODEL;
    #pragma unroll
    for (int dt = 0; dt < 8; dt++) {
        int col = dt * 8 + 2 * gc;
        *(float2*)(orow0 + col) = make_float2(oacc[dt][0] * inv0, oacc[dt][1] * inv0);
        *(float2*)(orow1 + col) = make_float2(oacc[dt][2] * inv1, oacc[dt][3] * inv1);
    }
}

// ============================================================================
extern "C" void kernel_launch(void* const* d_in, const int* in_sizes, int n_in,
                              void* d_out, int out_size)
{
    const float* q    = (const float*)d_in[0];
    const float* k    = (const float*)d_in[1];
    const float* v    = (const float*)d_in[2];
    const int*   mask = (const int*)  d_in[3];
    const float* wq   = (const float*)d_in[4];
    const float* bq   = (const float*)d_in[5];
    const float* wk   = (const float*)d_in[6];
    const float* bk   = (const float*)d_in[7];
    const float* wv   = (const float*)d_in[8];
    const float* bv   = (const float*)d_in[9];
    const float* wo   = (const float*)d_in[10];
    const float* bo   = (const float*)d_in[11];
    float* out = (float*)d_out;

    dim3 gg(D_MODEL / 128, MROWS / 128);   // (8, 32)
    tc_gemm<<<gg, 256>>>(q, wq, bq, nullptr, 0);
    tc_gemm<<<gg, 256>>>(k, wk, bk, nullptr, 1);
    tc_gemm<<<gg, 256>>>(v, wv, bv, nullptr, 2);   // V transposed in-epilogue
    attn_kernel<<<dim3(SS / 64, NH, BB), 128>>>(mask);   // 4th launch -> profiled
    tc_gemm<<<gg, 256>>>(nullptr, wo, bo, out, 3);
}